// round 12
// baseline (speedup 1.0000x reference)
#include <cuda_runtime.h>
#include <math.h>

// ---------------- problem constants ----------------
#define NATOMS 16384
#define NMOL   512
#define APM    32
#define FDIM   128
#define NRBF   20
#define FH     64
#define NLAY   3
#define PI_F   3.14159265358979f
#define CUT    5.0f
#define LOG2_F 0.6931471805599453f
#define TABN   1024

static const size_t NF = (size_t)NATOMS * FDIM;

typedef unsigned long long ull;

// ---------------- scratch ----------------
__device__ __align__(16) float  g_h    [3 * NF];
__device__ __align__(16) float  g_sig2 [3 * NF];
__device__ __align__(16) float  g_tabW [3 * TABN * FDIM];
__device__ __align__(16) float  g_tabD [3 * TABN * FDIM];
__device__ __align__(16) float4 g_tFW4 [3 * TABN * 64];   // fc*W   (v0,v1,s0,s1)
__device__ __align__(16) float4 g_tG4  [3 * TABN * 64];   // fc*D+dfc*W

__device__ __forceinline__ float sspf(float v) {
    return fmaxf(v, 0.f) + log1pf(expf(-fabsf(v))) - LOG2_F;
}
__device__ __forceinline__ ull pk2(float x) {
    ull r; asm("mov.b64 %0, {%1, %1};" : "=l"(r) : "f"(x)); return r;
}
__device__ __forceinline__ ull fma2(ull a, ull b, ull c) {
    ull d; asm("fma.rn.f32x2 %0, %1, %2, %3;" : "=l"(d) : "l"(a), "l"(b), "l"(c)); return d;
}
__device__ __forceinline__ ull mul2(ull a, ull b) {
    ull d; asm("mul.rn.f32x2 %0, %1, %2;" : "=l"(d) : "l"(a), "l"(b)); return d;
}
__device__ __forceinline__ float2 upk(ull v) {
    float2 r; asm("mov.b64 {%0, %1}, %2;" : "=f"(r.x), "=f"(r.y) : "l"(v)); return r;
}

// ---------------- filter table build (raw W, dW/dd) ----------------
__global__ __launch_bounds__(128) void table_k(
    const float* __restrict__ W1, const float* __restrict__ b1,
    const float* __restrict__ W2, const float* __restrict__ b2,
    float* __restrict__ tabW, float* __restrict__ tabD)
{
    const int t = blockIdx.x;
    const int l = blockIdx.y;
    const int f = threadIdx.x;
    const float DELTA = CUT / (NRBF-1);
    const float CO = -0.5f / (DELTA*DELTA);
    const float d = t * (CUT / (TABN-1));

    __shared__ float rbf_s[NRBF], drbf_s[NRBF];
    __shared__ float t1_s[FDIM], dt1_s[FDIM];
    if (f < NRBF) {
        float u = d - f*DELTA;
        float g = expf(CO*u*u);
        rbf_s[f]  = g;
        drbf_s[f] = g * (2.f*CO*u);
    }
    __syncthreads();

    const float* W1l = W1 + (size_t)l*NRBF*FDIM;
    float p = b1[l*FDIM + f], dp = 0.f;
    #pragma unroll
    for (int k=0;k<NRBF;k++) {
        float w = W1l[k*FDIM + f];
        p  = fmaf(rbf_s[k],  w, p);
        dp = fmaf(drbf_s[k], w, dp);
    }
    float sg = 1.f/(1.f+expf(-p));
    t1_s[f]  = sspf(p);
    dt1_s[f] = sg*dp;
    __syncthreads();

    const float* W2l = W2 + (size_t)l*FDIM*FDIM;
    float w = b2[l*FDIM + f], dw = 0.f;
    #pragma unroll 8
    for (int c=0;c<FDIM;c++) {
        float wv = W2l[c*FDIM + f];
        w  = fmaf(t1_s[c],  wv, w);
        dw = fmaf(dt1_s[c], wv, dw);
    }
    size_t o = ((size_t)l*TABN + t)*FDIM + f;
    tabW[o] = w;
    tabD[o] = dw;
}

__device__ __forceinline__ void fc_dfc(int t, float& fc, float& dfc) {
    float d = t * (CUT/(float)(TABN-1));
    float ang = PI_F * d * (1.f/CUT);
    fc  = 0.5f*(cosf(ang)+1.f);
    dfc = -(0.5f*PI_F/CUT)*sinf(ang);
}

// combined tables: FW = fc*W ; G = fc*D + dfc*W ; packed (v0,v1,s0,s1) per pair
__global__ __launch_bounds__(64) void combine4_k(
    const float* __restrict__ tabW, const float* __restrict__ tabD,
    float4* __restrict__ tFW4, float4* __restrict__ tG4)
{
    const int t = blockIdx.x, l = blockIdx.y, f = threadIdx.x; // pair 0..63
    size_t o  = ((size_t)l*TABN + t)*FDIM;
    size_t o4 = ((size_t)l*TABN + t)*64 + f;
    float fcA, dfcA, fcB, dfcB;
    fc_dfc(t, fcA, dfcA);
    int tB = (t < TABN-1) ? t+1 : t;
    fc_dfc(tB, fcB, dfcB);
    size_t oB = ((size_t)l*TABN + tB)*FDIM;

    float wA0 = tabW[o  + 2*f], wA1 = tabW[o  + 2*f + 1];
    float wB0 = tabW[oB + 2*f], wB1 = tabW[oB + 2*f + 1];
    float dA0 = tabD[o  + 2*f], dA1 = tabD[o  + 2*f + 1];
    float dB0 = tabD[oB + 2*f], dB1 = tabD[oB + 2*f + 1];

    float fwA0 = fcA*wA0, fwA1 = fcA*wA1;
    float fwB0 = fcB*wB0, fwB1 = fcB*wB1;
    tFW4[o4] = make_float4(fwA0, fwA1, fwB0 - fwA0, fwB1 - fwA1);

    float gA0 = fcA*dA0 + dfcA*wA0, gA1 = fcA*dA1 + dfcA*wA1;
    float gB0 = fcB*dB0 + dfcB*wB0, gB1 = fcB*dB1 + dfcB*wB1;
    tG4[o4] = make_float4(gA0, gA1, gB0 - gA0, gB1 - gA1);
}

// ---------------- GEMM: C(32x128) = A_s @ B, f32x2, K-split-2, 4x4 tiles ----
template<bool TRANSB>
__device__ __forceinline__ void ldW(float* Wd, const float* __restrict__ Bg,
                                    int k0, int tid)
{
    if (!TRANSB) {
        int row = tid>>5, c4 = (tid&31)<<2;
        *(float4*)&Wd[row*FDIM + c4] =
            *(const float4*)&Bg[(size_t)(k0+row)*FDIM + c4];
    } else {
        int c = tid>>2, kq = (tid&3)<<2;
        float4 w = *(const float4*)&Bg[(size_t)c*FDIM + k0 + kq];
        Wd[(kq+0)*FDIM + c] = w.x;
        Wd[(kq+1)*FDIM + c] = w.y;
        Wd[(kq+2)*FDIM + c] = w.z;
        Wd[(kq+3)*FDIM + c] = w.w;
    }
}

template<bool TRANSB>
__device__ __forceinline__ void gemm128(const float* __restrict__ A_s,
                                        const float* __restrict__ Bg,
                                        float* Ws, int tid, float out[4][4])
{
    const int kh = tid >> 8;
    const int t  = tid & 255;
    const int r4 = (t >> 5) << 2;
    const int c4 = (t & 31) << 2;
    ull acc[4][2] = {};
    ldW<TRANSB>(Ws, Bg, 0, tid);
    __syncthreads();
    for (int ch=0; ch<8; ch++) {
        const float* Wc = Ws + (ch&1)*2048;
        if (ch < 7) ldW<TRANSB>(Ws + ((ch+1)&1)*2048, Bg, (ch+1)*16, tid);
        if ((ch>>2) == kh) {
            const int k0 = ch*16;
            #pragma unroll
            for (int kk=0;kk<16;kk++) {
                ull a0 = pk2(A_s[(r4+0)*FDIM + k0+kk]);
                ull a1 = pk2(A_s[(r4+1)*FDIM + k0+kk]);
                ull a2 = pk2(A_s[(r4+2)*FDIM + k0+kk]);
                ull a3 = pk2(A_s[(r4+3)*FDIM + k0+kk]);
                ulonglong2 bp = *(const ulonglong2*)&Wc[kk*FDIM + c4];
                acc[0][0]=fma2(a0,bp.x,acc[0][0]); acc[0][1]=fma2(a0,bp.y,acc[0][1]);
                acc[1][0]=fma2(a1,bp.x,acc[1][0]); acc[1][1]=fma2(a1,bp.y,acc[1][1]);
                acc[2][0]=fma2(a2,bp.x,acc[2][0]); acc[2][1]=fma2(a2,bp.y,acc[2][1]);
                acc[3][0]=fma2(a3,bp.x,acc[3][0]); acc[3][1]=fma2(a3,bp.y,acc[3][1]);
            }
        }
        __syncthreads();
    }
    // reduce the two K-halves through Ws
    ull* buf = (ull*)Ws;
    if (kh == 1) {
        ull* bp = buf + t*8;
        #pragma unroll
        for (int m=0;m<4;m++) { bp[m*2]=acc[m][0]; bp[m*2+1]=acc[m][1]; }
    }
    __syncthreads();
    if (kh == 0) {
        const ull* bp = buf + t*8;
        #pragma unroll
        for (int m=0;m<4;m++) {
            float2 p0 = upk(acc[m][0]), q0 = upk(bp[m*2]);
            float2 p1 = upk(acc[m][1]), q1 = upk(bp[m*2+1]);
            out[m][0]=p0.x+q0.x; out[m][1]=p0.y+q0.y;
            out[m][2]=p1.x+q1.x; out[m][3]=p1.y+q1.y;
        }
    }
    __syncthreads();
}

// ---------------- smem pool (floats) ----------------
#define OFF_XS   0
#define OFF_HS   (OFF_XS + APM*FDIM)
#define OFF_AS   (OFF_HS + APM*FDIM)
#define OFF_TS   (OFF_AS + APM*FDIM)
#define OFF_WS   (OFF_TS + APM*FDIM)        // 2 x 2048 (also reduction buffer)
#define OFF_LI   (OFF_WS + 4096)            // float2[APM*31]
#define OFF_LJ   (OFF_LI + 2*APM*31)        // float2[APM*31]
#define OFF_GD   (OFF_LJ + 2*APM*31)
#define OFF_POS  (OFF_GD + APM*31)
#define OFF_CNT  (OFF_POS + 96)             // int[64]
#define OFF_ES   (OFF_CNT + 64)
#define SM_FLOATS (OFF_ES + 32)

__global__ __launch_bounds__(512,2) void mega_k(
    const float* __restrict__ pos, const float* __restrict__ emb,
    const int* __restrict__ Z,
    const float* __restrict__ in2f_W,
    const float* __restrict__ f2_W1, const float* __restrict__ f2_b1,
    const float* __restrict__ f2_W2, const float* __restrict__ f2_b2,
    const float* __restrict__ aw_W1, const float* __restrict__ aw_b1,
    const float* __restrict__ aw_W2, const float* __restrict__ aw_b2,
    const float4* __restrict__ tFW4g, const float4* __restrict__ tG4g,
    float* __restrict__ g_h_, float* __restrict__ g_sig2_,
    float* __restrict__ out)
{
    extern __shared__ float sm[];
    float*  Xs    = sm + OFF_XS;
    float*  Hs    = sm + OFF_HS;
    float*  As    = sm + OFF_AS;
    float*  Ts    = sm + OFF_TS;
    float*  Ws    = sm + OFF_WS;
    float2* liI   = (float2*)(sm + OFF_LI);
    float2* liJ   = (float2*)(sm + OFF_LJ);
    float*  gd_s  = sm + OFF_GD;
    float*  pos_s = sm + OFF_POS;
    int*    cntI  = (int*)(sm + OFF_CNT);
    int*    cntJ  = cntI + 32;
    float*  es    = sm + OFF_ES;

    const int tid = threadIdx.x;
    const int mol = blockIdx.x;
    const int abase = mol*APM;

    const int rg = tid>>5, cg = tid&31;
    const int r0 = rg<<1, c0 = cg<<2;           // head-section mapping
    const int q  = tid & 255;
    const int r4 = (q>>5)<<2, c4 = (q&31)<<2;   // GEMM epilogue mapping (tid<256)
    const int f2 = tid & 63, er = tid >> 6;     // edge-loop mapping

    // ---------- P0: pos, gather x, zero gd ----------
    if (tid < 96) pos_s[tid] = pos[abase*3 + tid];
    for (int t=tid; t<APM*FDIM/4; t+=512) {
        int a = t>>5, f4 = (t&31)<<2;
        int z = Z[abase + a];
        *(float4*)&Xs[a*FDIM + f4] = *(const float4*)&emb[(size_t)z*FDIM + f4];
    }
    for (int t=tid; t<APM*31; t+=512) gd_s[t] = 0.f;
    __syncthreads();

    // ---------- P0b: compacted edge lists ----------
    if (tid < 64) {
        const int role = tid >> 5;      // 0: by-i, 1: by-j
        const int a = tid & 31;
        int count = 0;
        for (int c=0; c<31; c++) {
            int other = c + (c >= a ? 1 : 0);
            int i = role==0 ? a : other;
            int j = role==0 ? other : a;
            float rx = pos_s[j*3+0]-pos_s[i*3+0];
            float ry = pos_s[j*3+1]-pos_s[i*3+1];
            float rz = pos_s[j*3+2]-pos_s[i*3+2];
            float d = sqrtf(rx*rx+ry*ry+rz*rz + 1e-12f);
            if (d < CUT) {
                float u = fminf(fmaxf(d*((float)(TABN-1)/CUT), 0.01f),
                                (float)(TABN-2) + 0.999f);
                float enc = (float)other*2048.f + u;
                if (role==0) liI[a*31+count] = make_float2(0.f, enc);
                else         liJ[a*31+count] = make_float2(0.f, enc);
                count++;
            }
        }
        if (role==0) cntI[a] = count; else cntJ[a] = count;
    }
    // (gemm128's leading sync publishes lists/Xs)

    // =============== forward layers ===============
    for (int l = 0; l < NLAY; l++) {
        const float* W0 = in2f_W + (size_t)l*FDIM*FDIM;
        const float* W1 = f2_W1  + (size_t)l*FDIM*FDIM;
        const float* W2 = f2_W2  + (size_t)l*FDIM*FDIM;
        const float2* tFW = (const float2*)(tFW4g + (size_t)l*TABN*64);
        float* s_g = g_sig2_ + (size_t)l*NF;
        float* h_g = g_h_ + (size_t)l*NF;

        float acc[4][4];
        // GEMM1: h = x @ W0 -> Hs (+global for l<2)
        gemm128<false>(Xs, W0, Ws, tid, acc);
        if (tid < 256) {
            #pragma unroll
            for (int m=0;m<4;m++) {
                float4 v = make_float4(acc[m][0],acc[m][1],acc[m][2],acc[m][3]);
                *(float4*)&Hs[(r4+m)*FDIM + c4] = v;
                if (l < 2)
                    *(float4*)&h_g[(size_t)(abase+r4+m)*FDIM + c4] = v;
            }
        }
        __syncthreads();

        // agg: As[i] = sum_j h[j] .* FW(d_ij)
        for (int it=0; it<4; it++) {
            int i = it*8 + er;
            int cnt = cntI[i];
            ull accp = 0ull;
            #pragma unroll 4
            for (int c=0;c<cnt;c++) {
                float enc = liI[i*31+c].y;
                int j = (int)(enc * (1.f/2048.f));
                float u = enc - (float)j*2048.f;
                int t0 = (int)u;
                float fr = u - (float)t0;
                ulonglong2 wv = *(const ulonglong2*)&tFW[((size_t)t0<<7) + 2*f2];
                ull w01 = fma2(pk2(fr), wv.y, wv.x);
                ull h01 = *(const ull*)&Hs[j*FDIM + 2*f2];
                accp = fma2(h01, w01, accp);
            }
            *(ull*)&As[i*FDIM + 2*f2] = accp;
        }

        // GEMM2: pre = agg@W1 + b1; sig2->global; t2=ssp->Ts
        gemm128<false>(As, W1, Ws, tid, acc);
        if (tid < 256) {
            float4 b1v = *(const float4*)&f2_b1[l*FDIM + c4];
            float bb[4]={b1v.x,b1v.y,b1v.z,b1v.w};
            #pragma unroll
            for (int m=0;m<4;m++) {
                float sg4[4];
                #pragma unroll
                for (int n=0;n<4;n++) {
                    float pre = acc[m][n] + bb[n];
                    sg4[n] = 1.f/(1.f+expf(-pre));
                    Ts[(r4+m)*FDIM + c4 + n] = sspf(pre);
                }
                *(float4*)&s_g[(size_t)(abase+r4+m)*FDIM + c4] =
                    make_float4(sg4[0],sg4[1],sg4[2],sg4[3]);
            }
        }

        // GEMM3: x += t2@W2 + b2
        gemm128<false>(Ts, W2, Ws, tid, acc);
        if (tid < 256) {
            float4 b2v = *(const float4*)&f2_b2[l*FDIM + c4];
            #pragma unroll
            for (int m=0;m<4;m++) {
                float* xp = &Xs[(r4+m)*FDIM + c4];
                xp[0] += acc[m][0] + b2v.x;
                xp[1] += acc[m][1] + b2v.y;
                xp[2] += acc[m][2] + b2v.z;
                xp[3] += acc[m][3] + b2v.w;
            }
        }
    }

    // =============== head: fwd + bwd ===============
    {
        if (tid < APM) es[tid] = 0.f;
        const int hc0 = cg<<1;
        float acc[2][2] = {};
        for (int k0=0;k0<FDIM;k0+=16) {
            __syncthreads();
            if (tid < 256) {
                int row = tid>>4, cc = (tid&15)<<2;
                *(float4*)&Ws[row*FH + cc] =
                    *(const float4*)&aw_W1[(size_t)(k0+row)*FH + cc];
            }
            __syncthreads();
            #pragma unroll
            for (int kk=0;kk<16;kk++) {
                float a0 = Xs[r0*FDIM + k0+kk];
                float a1 = Xs[(r0+1)*FDIM + k0+kk];
                float2 b = *(float2*)&Ws[kk*FH + hc0];
                acc[0][0]=fmaf(a0,b.x,acc[0][0]); acc[0][1]=fmaf(a0,b.y,acc[0][1]);
                acc[1][0]=fmaf(a1,b.x,acc[1][0]); acc[1][1]=fmaf(a1,b.y,acc[1][1]);
            }
        }
        float2 b1v = *(const float2*)&aw_b1[hc0];
        float2 w2v = *(const float2*)&aw_W2[hc0];
        float ep[2];
        #pragma unroll
        for (int m=0;m<2;m++) {
            float pre0 = acc[m][0] + b1v.x;
            float pre1 = acc[m][1] + b1v.y;
            float sg0 = 1.f/(1.f+expf(-pre0));
            float sg1 = 1.f/(1.f+expf(-pre1));
            ep[m] = sspf(pre0)*w2v.x + sspf(pre1)*w2v.y;
            Ts[(r0+m)*FH + hc0 + 0] = sg0*w2v.x;
            Ts[(r0+m)*FH + hc0 + 1] = sg1*w2v.y;
        }
        #pragma unroll
        for (int o=16;o>0;o>>=1) {
            ep[0] += __shfl_xor_sync(0xffffffffu, ep[0], o);
            ep[1] += __shfl_xor_sync(0xffffffffu, ep[1], o);
        }
        if (cg == 0) { es[r0] = ep[0]; es[r0+1] = ep[1]; }
        __syncthreads();
        if (tid == 0) {
            float s = APM * aw_b2[0];
            #pragma unroll
            for (int a=0;a<APM;a++) s += es[a];
            out[(size_t)3*NATOMS + mol] = s;
        }
        // GEMM2h: gx = gp @ aw_W1^T -> Xs
        float acc2[2][4] = {};
        for (int k0=0;k0<FH;k0+=16) {
            __syncthreads();
            {
                int f = tid>>2, kq = (tid&3)<<2;
                float4 w = *(const float4*)&aw_W1[(size_t)f*FH + k0 + kq];
                Ws[(kq+0)*FDIM + f] = w.x;
                Ws[(kq+1)*FDIM + f] = w.y;
                Ws[(kq+2)*FDIM + f] = w.z;
                Ws[(kq+3)*FDIM + f] = w.w;
            }
            __syncthreads();
            #pragma unroll
            for (int kk=0;kk<16;kk++) {
                float a0 = Ts[r0*FH + k0+kk];
                float a1 = Ts[(r0+1)*FH + k0+kk];
                float4 b = *(float4*)&Ws[kk*FDIM + c0];
                acc2[0][0]=fmaf(a0,b.x,acc2[0][0]); acc2[0][1]=fmaf(a0,b.y,acc2[0][1]);
                acc2[0][2]=fmaf(a0,b.z,acc2[0][2]); acc2[0][3]=fmaf(a0,b.w,acc2[0][3]);
                acc2[1][0]=fmaf(a1,b.x,acc2[1][0]); acc2[1][1]=fmaf(a1,b.y,acc2[1][1]);
                acc2[1][2]=fmaf(a1,b.z,acc2[1][2]); acc2[1][3]=fmaf(a1,b.w,acc2[1][3]);
            }
        }
        __syncthreads();
        #pragma unroll
        for (int m=0;m<2;m++)
            *(float4*)&Xs[(r0+m)*FDIM + c0] =
                make_float4(acc2[m][0],acc2[m][1],acc2[m][2],acc2[m][3]);
    }

    // =============== backward layers ===============
    for (int l = NLAY-1; l >= 0; l--) {
        const float* W0 = in2f_W + (size_t)l*FDIM*FDIM;
        const float* W1 = f2_W1  + (size_t)l*FDIM*FDIM;
        const float* W2 = f2_W2  + (size_t)l*FDIM*FDIM;
        const float2* tFW = (const float2*)(tFW4g + (size_t)l*TABN*64);
        const float4* tG  = tG4g  + (size_t)l*TABN*64;
        const float* s_g = g_sig2_ + (size_t)l*NF;
        const float* h_g = g_h_ + (size_t)l*NF;

        if (l < 2) {   // Hs for l==2 persists from forward
            for (int t=tid; t<APM*FDIM/4; t+=512) {
                int a = t>>5, f4 = (t&31)<<2;
                *(float4*)&Hs[a*FDIM + f4] =
                    *(const float4*)&h_g[(size_t)(abase+a)*FDIM + f4];
            }
        }

        float acc[4][4];
        // GEMM1: gpre2 = (gx @ W2^T)*sig2 -> Ts
        gemm128<true>(Xs, W2, Ws, tid, acc);
        if (tid < 256) {
            #pragma unroll
            for (int m=0;m<4;m++) {
                float4 s4 = *(const float4*)&s_g[(size_t)(abase+r4+m)*FDIM + c4];
                Ts[(r4+m)*FDIM + c4 + 0] = acc[m][0]*s4.x;
                Ts[(r4+m)*FDIM + c4 + 1] = acc[m][1]*s4.y;
                Ts[(r4+m)*FDIM + c4 + 2] = acc[m][2]*s4.z;
                Ts[(r4+m)*FDIM + c4 + 3] = acc[m][3]*s4.w;
            }
        }

        // GEMM2: ga = gpre2 @ W1^T -> As
        gemm128<true>(Ts, W1, Ws, tid, acc);
        if (tid < 256) {
            #pragma unroll
            for (int m=0;m<4;m++)
                *(float4*)&As[(r4+m)*FDIM + c4] =
                    make_float4(acc[m][0],acc[m][1],acc[m][2],acc[m][3]);
        }
        __syncthreads();

        // gh phase: Ts[j] = sum_i ga[i] .* FW(d_ij)
        for (int jt=0; jt<4; jt++) {
            int j = jt*8 + er;
            int cnt = cntJ[j];
            ull accp = 0ull;
            #pragma unroll 4
            for (int c=0;c<cnt;c++) {
                float enc = liJ[j*31+c].y;
                int i = (int)(enc * (1.f/2048.f));
                float u = enc - (float)i*2048.f;
                int t0 = (int)u;
                float fr = u - (float)t0;
                ulonglong2 wv = *(const ulonglong2*)&tFW[((size_t)t0<<7) + 2*f2];
                ull w01 = fma2(pk2(fr), wv.y, wv.x);
                ull ga = *(const ull*)&As[i*FDIM + 2*f2];
                accp = fma2(ga, w01, accp);
            }
            *(ull*)&Ts[j*FDIM + 2*f2] = accp;
        }

        // gd phase: warp-per-edge, combined table G, ga hoisted
        // lane owns features 4*lane..4*lane+3 -> table PAIRS 2*lane, 2*lane+1
        {
            const int warp = tid >> 5, lane = cg;
            #pragma unroll
            for (int rr=0; rr<2; rr++) {
                int i = (warp<<1) + rr;
                int cnt = cntI[i];
                ulonglong2 gaP = *(const ulonglong2*)&As[i*FDIM + (lane<<2)];
                #pragma unroll 4
                for (int c=0;c<cnt;c++) {
                    float enc = liI[i*31+c].y;
                    int j = (int)(enc * (1.f/2048.f));
                    float u = enc - (float)j*2048.f;
                    int t0 = (int)u;
                    ull frp = pk2(u - (float)t0);
                    const float4* tg = tG + ((size_t)t0<<6);
                    ulonglong2 gv0 = *(const ulonglong2*)&tg[2*lane];      // pair 2l
                    ulonglong2 gv1 = *(const ulonglong2*)&tg[2*lane + 1];  // pair 2l+1
                    ulonglong2 hv = *(const ulonglong2*)&Hs[j*FDIM + (lane<<2)];
                    ull s = mul2(mul2(gaP.x, hv.x), fma2(frp, gv0.y, gv0.x));
                    s = fma2(mul2(gaP.y, hv.y), fma2(frp, gv1.y, gv1.x), s);
                    float2 sv = upk(s);
                    float term = sv.x + sv.y;
                    #pragma unroll
                    for (int o=16;o>0;o>>=1)
                        term += __shfl_xor_sync(0xffffffffu, term, o);
                    if (lane == 0) gd_s[i*31+c] += term;
                }
            }
        }

        // GEMM3: gx += gh @ W0^T
        gemm128<true>(Ts, W0, Ws, tid, acc);
        if (tid < 256) {
            #pragma unroll
            for (int m=0;m<4;m++) {
                float* gp = &Xs[(r4+m)*FDIM + c4];
                gp[0] += acc[m][0]; gp[1] += acc[m][1];
                gp[2] += acc[m][2]; gp[3] += acc[m][3];
            }
        }
    }
    __syncthreads();

    // =============== action ===============
    {
        float* gp  = Ws;
        float* nrm = Ws + 96;
        float* cf  = Ws + 128;
        if (tid < 96) gp[tid] = 0.f;
        __syncthreads();
        for (int el=tid; el<APM*31; el+=512) {
            int i = el / 31, slot = el - i*31;
            if (slot < cntI[i]) {
                float enc = liI[el].y;
                int j = (int)(enc * (1.f/2048.f));
                float u = enc - (float)j*2048.f;
                float d = u * (CUT/(float)(TABN-1));
                float g = gd_s[el] / d;
                float rx = pos_s[j*3+0]-pos_s[i*3+0];
                float ry = pos_s[j*3+1]-pos_s[i*3+1];
                float rz = pos_s[j*3+2]-pos_s[i*3+2];
                atomicAdd(&gp[j*3+0],  g*rx); atomicAdd(&gp[j*3+1],  g*ry);
                atomicAdd(&gp[j*3+2],  g*rz);
                atomicAdd(&gp[i*3+0], -g*rx); atomicAdd(&gp[i*3+1], -g*ry);
                atomicAdd(&gp[i*3+2], -g*rz);
            }
        }
        __syncthreads();
        if (tid < APM) {
            float ax = gp[tid*3+0], ay = gp[tid*3+1], az = gp[tid*3+2];
            nrm[tid] = sqrtf(ax*ax + ay*ay + az*az);
        }
        __syncthreads();
        if (tid == 0) {
            float mx = 0.f;
            #pragma unroll
            for (int a=0;a<APM;a++) mx = fmaxf(mx, nrm[a]);
            cf[0] = fminf(1.0f / fmaxf(mx, 1e-8f), 1.0f);
        }
        __syncthreads();
        float coef = cf[0];
        for (int t=tid; t<96; t+=512)
            out[(size_t)abase*3 + t] = -gp[t]*coef;
    }
}

// ---------------- host ----------------
static const int MEGA_SMEM = SM_FLOATS * 4;

extern "C" void kernel_launch(void* const* d_in, const int* in_sizes, int n_in,
                              void* d_out, int out_size)
{
    const float* positions = (const float*)d_in[0];
    const float* emb       = (const float*)d_in[1];
    const float* in2f_W    = (const float*)d_in[2];
    const float* filt_W1   = (const float*)d_in[3];
    const float* filt_b1   = (const float*)d_in[4];
    const float* filt_W2   = (const float*)d_in[5];
    const float* filt_b2   = (const float*)d_in[6];
    const float* f2_W1     = (const float*)d_in[7];
    const float* f2_b1     = (const float*)d_in[8];
    const float* f2_W2     = (const float*)d_in[9];
    const float* f2_b2     = (const float*)d_in[10];
    const float* aw_W1     = (const float*)d_in[11];
    const float* aw_b1     = (const float*)d_in[12];
    const float* aw_W2     = (const float*)d_in[13];
    const float* aw_b2     = (const float*)d_in[14];
    const int*   Z         = (const int*)d_in[15];
    float* out = (float*)d_out;

    float *p_h, *p_sig2, *p_tabW, *p_tabD;
    float4 *p_tFW4, *p_tG4;
    cudaGetSymbolAddress((void**)&p_h,     g_h);
    cudaGetSymbolAddress((void**)&p_sig2,  g_sig2);
    cudaGetSymbolAddress((void**)&p_tabW,  g_tabW);
    cudaGetSymbolAddress((void**)&p_tabD,  g_tabD);
    cudaGetSymbolAddress((void**)&p_tFW4,  g_tFW4);
    cudaGetSymbolAddress((void**)&p_tG4,   g_tG4);

    cudaFuncSetAttribute(mega_k, cudaFuncAttributeMaxDynamicSharedMemorySize,
                         MEGA_SMEM);

    table_k<<<dim3(TABN,3),128>>>(filt_W1, filt_b1, filt_W2, filt_b2,
                                  p_tabW, p_tabD);
    combine4_k<<<dim3(TABN,3),64>>>(p_tabW, p_tabD, p_tFW4, p_tG4);
    mega_k<<<NMOL, 512, MEGA_SMEM>>>(
        positions, emb, Z, in2f_W,
        f2_W1, f2_b1, f2_W2, f2_b2,
        aw_W1, aw_b1, aw_W2, aw_b2,
        p_tFW4, p_tG4, p_h, p_sig2, out);
}

// round 13
// speedup vs baseline: 1.1255x; 1.1255x over previous
#include <cuda_runtime.h>
#include <math.h>

// ---------------- problem constants ----------------
#define NATOMS 16384
#define NMOL   512
#define APM    32
#define FDIM   128
#define NRBF   20
#define FH     64
#define NLAY   3
#define PI_F   3.14159265358979f
#define CUT    5.0f
#define LOG2_F 0.6931471805599453f
#define TABN   1024
#define TABF   16384

static const size_t NF = (size_t)NATOMS * FDIM;

typedef unsigned long long ull;

// ---------------- scratch ----------------
__device__ __align__(16) float  g_h    [3 * NF];
__device__ __align__(16) float  g_sig2 [3 * NF];
__device__ __align__(16) float  g_tabW [3 * TABN * FDIM];
__device__ __align__(16) float  g_tabD [3 * TABN * FDIM];
__device__ __align__(16) float  g_FWn  [3 * (size_t)TABF * FDIM];  // fc*W, fine grid
__device__ __align__(16) float  g_Gn   [3 * (size_t)TABF * FDIM];  // fc*D+dfc*W

__device__ __forceinline__ float sspf(float v) {
    return fmaxf(v, 0.f) + log1pf(expf(-fabsf(v))) - LOG2_F;
}
__device__ __forceinline__ ull pk2(float x) {
    ull r; asm("mov.b64 %0, {%1, %1};" : "=l"(r) : "f"(x)); return r;
}
__device__ __forceinline__ ull fma2(ull a, ull b, ull c) {
    ull d; asm("fma.rn.f32x2 %0, %1, %2, %3;" : "=l"(d) : "l"(a), "l"(b), "l"(c)); return d;
}
__device__ __forceinline__ ull mul2(ull a, ull b) {
    ull d; asm("mul.rn.f32x2 %0, %1, %2;" : "=l"(d) : "l"(a), "l"(b)); return d;
}
__device__ __forceinline__ float2 upk(ull v) {
    float2 r; asm("mov.b64 {%0, %1}, %2;" : "=f"(r.x), "=f"(r.y) : "l"(v)); return r;
}

// ---------------- coarse table build (raw W, dW/dd; exact analytic) ----------------
__global__ __launch_bounds__(128) void table_k(
    const float* __restrict__ W1, const float* __restrict__ b1,
    const float* __restrict__ W2, const float* __restrict__ b2,
    float* __restrict__ tabW, float* __restrict__ tabD)
{
    const int t = blockIdx.x;
    const int l = blockIdx.y;
    const int f = threadIdx.x;
    const float DELTA = CUT / (NRBF-1);
    const float CO = -0.5f / (DELTA*DELTA);
    const float d = t * (CUT / (TABN-1));

    __shared__ float rbf_s[NRBF], drbf_s[NRBF];
    __shared__ float t1_s[FDIM], dt1_s[FDIM];
    if (f < NRBF) {
        float u = d - f*DELTA;
        float g = expf(CO*u*u);
        rbf_s[f]  = g;
        drbf_s[f] = g * (2.f*CO*u);
    }
    __syncthreads();

    const float* W1l = W1 + (size_t)l*NRBF*FDIM;
    float p = b1[l*FDIM + f], dp = 0.f;
    #pragma unroll
    for (int k=0;k<NRBF;k++) {
        float w = W1l[k*FDIM + f];
        p  = fmaf(rbf_s[k],  w, p);
        dp = fmaf(drbf_s[k], w, dp);
    }
    float sg = 1.f/(1.f+expf(-p));
    t1_s[f]  = sspf(p);
    dt1_s[f] = sg*dp;
    __syncthreads();

    const float* W2l = W2 + (size_t)l*FDIM*FDIM;
    float w = b2[l*FDIM + f], dw = 0.f;
    #pragma unroll 8
    for (int c=0;c<FDIM;c++) {
        float wv = W2l[c*FDIM + f];
        w  = fmaf(t1_s[c],  wv, w);
        dw = fmaf(dt1_s[c], wv, dw);
    }
    size_t o = ((size_t)l*TABN + t)*FDIM + f;
    tabW[o] = w;
    tabD[o] = dw;
}

// ---------------- upsample to fine nearest-neighbor tables ----------------
__global__ __launch_bounds__(128) void upsample_k(
    const float* __restrict__ tabW, const float* __restrict__ tabD,
    float* __restrict__ FWn, float* __restrict__ Gn)
{
    const int T = blockIdx.x, l = blockIdx.y, f = threadIdx.x;
    const float dfine = T * (CUT/(float)(TABF-1));
    float x = dfine * ((float)(TABN-1)/CUT);
    int t0 = (int)x; if (t0 > TABN-2) t0 = TABN-2;
    float fr = x - (float)t0;
    size_t oc = ((size_t)l*TABN + t0)*FDIM + f;
    float w0 = tabW[oc], w1 = tabW[oc+FDIM];
    float d0 = tabD[oc], d1 = tabD[oc+FDIM];
    float w = fmaf(fr, w1-w0, w0);
    float dd = fmaf(fr, d1-d0, d0);
    float ang = PI_F * dfine * (1.f/CUT);
    float fc  = 0.5f*(cosf(ang)+1.f);
    float dfc = -(0.5f*PI_F/CUT)*sinf(ang);
    size_t of = ((size_t)l*TABF + T)*FDIM + f;
    FWn[of] = fc*w;
    Gn[of]  = fmaf(fc, dd, dfc*w);
}

// ---------------- GEMM: C(32x128) = A_s @ B, f32x2, K-split-2, 4x4 tiles ----
template<bool TRANSB>
__device__ __forceinline__ void ldW(float* Wd, const float* __restrict__ Bg,
                                    int k0, int tid)
{
    if (!TRANSB) {
        int row = tid>>5, c4 = (tid&31)<<2;
        *(float4*)&Wd[row*FDIM + c4] =
            *(const float4*)&Bg[(size_t)(k0+row)*FDIM + c4];
    } else {
        int c = tid>>2, kq = (tid&3)<<2;
        float4 w = *(const float4*)&Bg[(size_t)c*FDIM + k0 + kq];
        Wd[(kq+0)*FDIM + c] = w.x;
        Wd[(kq+1)*FDIM + c] = w.y;
        Wd[(kq+2)*FDIM + c] = w.z;
        Wd[(kq+3)*FDIM + c] = w.w;
    }
}

template<bool TRANSB>
__device__ __forceinline__ void gemm128(const float* __restrict__ A_s,
                                        const float* __restrict__ Bg,
                                        float* Ws, int tid, float out[4][4])
{
    const int kh = tid >> 8;
    const int t  = tid & 255;
    const int r4 = (t >> 5) << 2;
    const int c4 = (t & 31) << 2;
    ull acc[4][2] = {};
    ldW<TRANSB>(Ws, Bg, 0, tid);
    __syncthreads();
    for (int ch=0; ch<8; ch++) {
        const float* Wc = Ws + (ch&1)*2048;
        if (ch < 7) ldW<TRANSB>(Ws + ((ch+1)&1)*2048, Bg, (ch+1)*16, tid);
        if ((ch>>2) == kh) {
            const int k0 = ch*16;
            #pragma unroll
            for (int kk=0;kk<16;kk++) {
                ull a0 = pk2(A_s[(r4+0)*FDIM + k0+kk]);
                ull a1 = pk2(A_s[(r4+1)*FDIM + k0+kk]);
                ull a2 = pk2(A_s[(r4+2)*FDIM + k0+kk]);
                ull a3 = pk2(A_s[(r4+3)*FDIM + k0+kk]);
                ulonglong2 bp = *(const ulonglong2*)&Wc[kk*FDIM + c4];
                acc[0][0]=fma2(a0,bp.x,acc[0][0]); acc[0][1]=fma2(a0,bp.y,acc[0][1]);
                acc[1][0]=fma2(a1,bp.x,acc[1][0]); acc[1][1]=fma2(a1,bp.y,acc[1][1]);
                acc[2][0]=fma2(a2,bp.x,acc[2][0]); acc[2][1]=fma2(a2,bp.y,acc[2][1]);
                acc[3][0]=fma2(a3,bp.x,acc[3][0]); acc[3][1]=fma2(a3,bp.y,acc[3][1]);
            }
        }
        __syncthreads();
    }
    ull* buf = (ull*)Ws;
    if (kh == 1) {
        ull* bp = buf + t*8;
        #pragma unroll
        for (int m=0;m<4;m++) { bp[m*2]=acc[m][0]; bp[m*2+1]=acc[m][1]; }
    }
    __syncthreads();
    if (kh == 0) {
        const ull* bp = buf + t*8;
        #pragma unroll
        for (int m=0;m<4;m++) {
            float2 p0 = upk(acc[m][0]), q0 = upk(bp[m*2]);
            float2 p1 = upk(acc[m][1]), q1 = upk(bp[m*2+1]);
            out[m][0]=p0.x+q0.x; out[m][1]=p0.y+q0.y;
            out[m][2]=p1.x+q1.x; out[m][3]=p1.y+q1.y;
        }
    }
    __syncthreads();
}

// ---------------- smem pool (floats) ----------------
#define OFF_XS   0
#define OFF_HS   (OFF_XS + APM*FDIM)
#define OFF_AS   (OFF_HS + APM*FDIM)
#define OFF_TS   (OFF_AS + APM*FDIM)
#define OFF_WS   (OFF_TS + APM*FDIM)        // 2 x 2048 (also reduction buffer)
#define OFF_LI   (OFF_WS + 4096)            // float[APM*31]
#define OFF_LJ   (OFF_LI + APM*31)
#define OFF_GD   (OFF_LJ + APM*31)
#define OFF_POS  (OFF_GD + APM*31)
#define OFF_CNT  (OFF_POS + 96)             // int[64]
#define OFF_ES   (OFF_CNT + 64)
#define SM_FLOATS (OFF_ES + 32)

__global__ __launch_bounds__(512,2) void mega_k(
    const float* __restrict__ pos, const float* __restrict__ emb,
    const int* __restrict__ Z,
    const float* __restrict__ in2f_W,
    const float* __restrict__ f2_W1, const float* __restrict__ f2_b1,
    const float* __restrict__ f2_W2, const float* __restrict__ f2_b2,
    const float* __restrict__ aw_W1, const float* __restrict__ aw_b1,
    const float* __restrict__ aw_W2, const float* __restrict__ aw_b2,
    const float* __restrict__ FWng, const float* __restrict__ Gng,
    float* __restrict__ g_h_, float* __restrict__ g_sig2_,
    float* __restrict__ out)
{
    extern __shared__ float sm[];
    float*  Xs    = sm + OFF_XS;
    float*  Hs    = sm + OFF_HS;
    float*  As    = sm + OFF_AS;
    float*  Ts    = sm + OFF_TS;
    float*  Ws    = sm + OFF_WS;
    float*  liI   = sm + OFF_LI;
    float*  liJ   = sm + OFF_LJ;
    float*  gd_s  = sm + OFF_GD;
    float*  pos_s = sm + OFF_POS;
    int*    cntI  = (int*)(sm + OFF_CNT);
    int*    cntJ  = cntI + 32;
    float*  es    = sm + OFF_ES;

    const int tid = threadIdx.x;
    const int mol = blockIdx.x;
    const int abase = mol*APM;

    const int rg = tid>>5, cg = tid&31;
    const int r0 = rg<<1, c0 = cg<<2;           // head-section mapping
    const int q  = tid & 255;
    const int r4 = (q>>5)<<2, c4 = (q&31)<<2;   // GEMM epilogue (tid<256)
    const int slot = tid>>5, lane = tid&31;     // edge loops: 16 slots x 32 lanes
    const int l4 = lane<<2;

    // ---------- P0: pos, gather x, zero gd ----------
    if (tid < 96) pos_s[tid] = pos[abase*3 + tid];
    for (int t=tid; t<APM*FDIM/4; t+=512) {
        int a = t>>5, f4 = (t&31)<<2;
        int z = Z[abase + a];
        *(float4*)&Xs[a*FDIM + f4] = *(const float4*)&emb[(size_t)z*FDIM + f4];
    }
    for (int t=tid; t<APM*31; t+=512) gd_s[t] = 0.f;
    __syncthreads();

    // ---------- P0b: compacted edge lists (packed int: other<<14 | T) ----------
    if (tid < 64) {
        const int role = tid >> 5;      // 0: by-i, 1: by-j
        const int a = tid & 31;
        int count = 0;
        for (int c=0; c<31; c++) {
            int other = c + (c >= a ? 1 : 0);
            int i = role==0 ? a : other;
            int j = role==0 ? other : a;
            float rx = pos_s[j*3+0]-pos_s[i*3+0];
            float ry = pos_s[j*3+1]-pos_s[i*3+1];
            float rz = pos_s[j*3+2]-pos_s[i*3+2];
            float d = sqrtf(rx*rx+ry*ry+rz*rz + 1e-12f);
            if (d < CUT) {
                int T = (int)(d * ((float)(TABF-1)/CUT) + 0.5f);
                if (T > TABF-1) T = TABF-1;
                int pk = (other << 14) | T;
                float rec = __int_as_float(pk);
                if (role==0) liI[a*31+count] = rec;
                else         liJ[a*31+count] = rec;
                count++;
            }
        }
        if (role==0) cntI[a] = count; else cntJ[a] = count;
    }
    // (gemm128's leading sync publishes lists/Xs)

    // =============== forward layers ===============
    for (int l = 0; l < NLAY; l++) {
        const float* W0 = in2f_W + (size_t)l*FDIM*FDIM;
        const float* W1 = f2_W1  + (size_t)l*FDIM*FDIM;
        const float* W2 = f2_W2  + (size_t)l*FDIM*FDIM;
        const float* FWl = FWng + (size_t)l*TABF*FDIM;
        float* s_g = g_sig2_ + (size_t)l*NF;
        float* h_g = g_h_ + (size_t)l*NF;

        float acc[4][4];
        // GEMM1: h = x @ W0 -> Hs (+global for l<2)
        gemm128<false>(Xs, W0, Ws, tid, acc);
        if (tid < 256) {
            #pragma unroll
            for (int m=0;m<4;m++) {
                float4 v = make_float4(acc[m][0],acc[m][1],acc[m][2],acc[m][3]);
                *(float4*)&Hs[(r4+m)*FDIM + c4] = v;
                if (l < 2)
                    *(float4*)&h_g[(size_t)(abase+r4+m)*FDIM + c4] = v;
            }
        }
        __syncthreads();

        // agg: As[i] = sum_j h[j] .* FW(d_ij), lane owns features 4l..4l+3
        #pragma unroll
        for (int it=0; it<2; it++) {
            int i = it*16 + slot;
            int cnt = cntI[i];
            ull a0=0ull, a1=0ull;
            for (int c=0;c<cnt;c++) {
                int pk = __float_as_int(liI[i*31+c]);
                int j = pk >> 14;
                int T = pk & 16383;
                ulonglong2 w = *(const ulonglong2*)&FWl[(size_t)T*FDIM + l4];
                ulonglong2 h = *(const ulonglong2*)&Hs[j*FDIM + l4];
                a0 = fma2(h.x, w.x, a0);
                a1 = fma2(h.y, w.y, a1);
            }
            ulonglong2 r; r.x=a0; r.y=a1;
            *(ulonglong2*)&As[i*FDIM + l4] = r;
        }

        // GEMM2: pre = agg@W1 + b1; sig2->global; t2=ssp->Ts
        gemm128<false>(As, W1, Ws, tid, acc);
        if (tid < 256) {
            float4 b1v = *(const float4*)&f2_b1[l*FDIM + c4];
            float bb[4]={b1v.x,b1v.y,b1v.z,b1v.w};
            #pragma unroll
            for (int m=0;m<4;m++) {
                float sg4[4];
                #pragma unroll
                for (int n=0;n<4;n++) {
                    float pre = acc[m][n] + bb[n];
                    sg4[n] = 1.f/(1.f+expf(-pre));
                    Ts[(r4+m)*FDIM + c4 + n] = sspf(pre);
                }
                *(float4*)&s_g[(size_t)(abase+r4+m)*FDIM + c4] =
                    make_float4(sg4[0],sg4[1],sg4[2],sg4[3]);
            }
        }

        // GEMM3: x += t2@W2 + b2
        gemm128<false>(Ts, W2, Ws, tid, acc);
        if (tid < 256) {
            float4 b2v = *(const float4*)&f2_b2[l*FDIM + c4];
            #pragma unroll
            for (int m=0;m<4;m++) {
                float* xp = &Xs[(r4+m)*FDIM + c4];
                xp[0] += acc[m][0] + b2v.x;
                xp[1] += acc[m][1] + b2v.y;
                xp[2] += acc[m][2] + b2v.z;
                xp[3] += acc[m][3] + b2v.w;
            }
        }
    }

    // =============== head: fwd + bwd ===============
    {
        if (tid < APM) es[tid] = 0.f;
        const int hc0 = cg<<1;
        float acc[2][2] = {};
        for (int k0=0;k0<FDIM;k0+=16) {
            __syncthreads();
            if (tid < 256) {
                int row = tid>>4, cc = (tid&15)<<2;
                *(float4*)&Ws[row*FH + cc] =
                    *(const float4*)&aw_W1[(size_t)(k0+row)*FH + cc];
            }
            __syncthreads();
            #pragma unroll
            for (int kk=0;kk<16;kk++) {
                float a0 = Xs[r0*FDIM + k0+kk];
                float a1 = Xs[(r0+1)*FDIM + k0+kk];
                float2 b = *(float2*)&Ws[kk*FH + hc0];
                acc[0][0]=fmaf(a0,b.x,acc[0][0]); acc[0][1]=fmaf(a0,b.y,acc[0][1]);
                acc[1][0]=fmaf(a1,b.x,acc[1][0]); acc[1][1]=fmaf(a1,b.y,acc[1][1]);
            }
        }
        float2 b1v = *(const float2*)&aw_b1[hc0];
        float2 w2v = *(const float2*)&aw_W2[hc0];
        float ep[2];
        #pragma unroll
        for (int m=0;m<2;m++) {
            float pre0 = acc[m][0] + b1v.x;
            float pre1 = acc[m][1] + b1v.y;
            float sg0 = 1.f/(1.f+expf(-pre0));
            float sg1 = 1.f/(1.f+expf(-pre1));
            ep[m] = sspf(pre0)*w2v.x + sspf(pre1)*w2v.y;
            Ts[(r0+m)*FH + hc0 + 0] = sg0*w2v.x;
            Ts[(r0+m)*FH + hc0 + 1] = sg1*w2v.y;
        }
        #pragma unroll
        for (int o=16;o>0;o>>=1) {
            ep[0] += __shfl_xor_sync(0xffffffffu, ep[0], o);
            ep[1] += __shfl_xor_sync(0xffffffffu, ep[1], o);
        }
        if (cg == 0) { es[r0] = ep[0]; es[r0+1] = ep[1]; }
        __syncthreads();
        if (tid == 0) {
            float s = APM * aw_b2[0];
            #pragma unroll
            for (int a=0;a<APM;a++) s += es[a];
            out[(size_t)3*NATOMS + mol] = s;
        }
        // GEMM2h: gx = gp @ aw_W1^T -> Xs
        float acc2[2][4] = {};
        for (int k0=0;k0<FH;k0+=16) {
            __syncthreads();
            {
                int f = tid>>2, kq = (tid&3)<<2;
                float4 w = *(const float4*)&aw_W1[(size_t)f*FH + k0 + kq];
                Ws[(kq+0)*FDIM + f] = w.x;
                Ws[(kq+1)*FDIM + f] = w.y;
                Ws[(kq+2)*FDIM + f] = w.z;
                Ws[(kq+3)*FDIM + f] = w.w;
            }
            __syncthreads();
            #pragma unroll
            for (int kk=0;kk<16;kk++) {
                float a0 = Ts[r0*FH + k0+kk];
                float a1 = Ts[(r0+1)*FH + k0+kk];
                float4 b = *(float4*)&Ws[kk*FDIM + c0];
                acc2[0][0]=fmaf(a0,b.x,acc2[0][0]); acc2[0][1]=fmaf(a0,b.y,acc2[0][1]);
                acc2[0][2]=fmaf(a0,b.z,acc2[0][2]); acc2[0][3]=fmaf(a0,b.w,acc2[0][3]);
                acc2[1][0]=fmaf(a1,b.x,acc2[1][0]); acc2[1][1]=fmaf(a1,b.y,acc2[1][1]);
                acc2[1][2]=fmaf(a1,b.z,acc2[1][2]); acc2[1][3]=fmaf(a1,b.w,acc2[1][3]);
            }
        }
        __syncthreads();
        #pragma unroll
        for (int m=0;m<2;m++)
            *(float4*)&Xs[(r0+m)*FDIM + c0] =
                make_float4(acc2[m][0],acc2[m][1],acc2[m][2],acc2[m][3]);
    }

    // =============== backward layers ===============
    for (int l = NLAY-1; l >= 0; l--) {
        const float* W0 = in2f_W + (size_t)l*FDIM*FDIM;
        const float* W1 = f2_W1  + (size_t)l*FDIM*FDIM;
        const float* W2 = f2_W2  + (size_t)l*FDIM*FDIM;
        const float* FWl = FWng + (size_t)l*TABF*FDIM;
        const float* Gl  = Gng  + (size_t)l*TABF*FDIM;
        const float* s_g = g_sig2_ + (size_t)l*NF;
        const float* h_g = g_h_ + (size_t)l*NF;

        if (l < 2) {   // Hs for l==2 persists from forward
            for (int t=tid; t<APM*FDIM/4; t+=512) {
                int a = t>>5, f4 = (t&31)<<2;
                *(float4*)&Hs[a*FDIM + f4] =
                    *(const float4*)&h_g[(size_t)(abase+a)*FDIM + f4];
            }
        }

        float acc[4][4];
        // GEMM1: gpre2 = (gx @ W2^T)*sig2 -> Ts
        gemm128<true>(Xs, W2, Ws, tid, acc);
        if (tid < 256) {
            #pragma unroll
            for (int m=0;m<4;m++) {
                float4 s4 = *(const float4*)&s_g[(size_t)(abase+r4+m)*FDIM + c4];
                Ts[(r4+m)*FDIM + c4 + 0] = acc[m][0]*s4.x;
                Ts[(r4+m)*FDIM + c4 + 1] = acc[m][1]*s4.y;
                Ts[(r4+m)*FDIM + c4 + 2] = acc[m][2]*s4.z;
                Ts[(r4+m)*FDIM + c4 + 3] = acc[m][3]*s4.w;
            }
        }

        // GEMM2: ga = gpre2 @ W1^T -> As
        gemm128<true>(Ts, W1, Ws, tid, acc);
        if (tid < 256) {
            #pragma unroll
            for (int m=0;m<4;m++)
                *(float4*)&As[(r4+m)*FDIM + c4] =
                    make_float4(acc[m][0],acc[m][1],acc[m][2],acc[m][3]);
        }
        __syncthreads();

        // gh phase: Ts[j] = sum_i ga[i] .* FW(d_ij)
        #pragma unroll
        for (int it=0; it<2; it++) {
            int j = it*16 + slot;
            int cnt = cntJ[j];
            ull a0=0ull, a1=0ull;
            for (int c=0;c<cnt;c++) {
                int pk = __float_as_int(liJ[j*31+c]);
                int i = pk >> 14;
                int T = pk & 16383;
                ulonglong2 w = *(const ulonglong2*)&FWl[(size_t)T*FDIM + l4];
                ulonglong2 ga = *(const ulonglong2*)&As[i*FDIM + l4];
                a0 = fma2(ga.x, w.x, a0);
                a1 = fma2(ga.y, w.y, a1);
            }
            ulonglong2 r; r.x=a0; r.y=a1;
            *(ulonglong2*)&Ts[j*FDIM + l4] = r;
        }

        // gd phase: warp-per-edge-row, single combined table G
        {
            const int warp = tid >> 5;
            #pragma unroll
            for (int rr=0; rr<2; rr++) {
                int i = (warp<<1) + rr;
                int cnt = cntI[i];
                ulonglong2 gaP = *(const ulonglong2*)&As[i*FDIM + l4];
                for (int c=0;c<cnt;c++) {
                    int pk = __float_as_int(liI[i*31+c]);
                    int j = pk >> 14;
                    int T = pk & 16383;
                    ulonglong2 gv = *(const ulonglong2*)&Gl[(size_t)T*FDIM + l4];
                    ulonglong2 hv = *(const ulonglong2*)&Hs[j*FDIM + l4];
                    ull s = mul2(mul2(gaP.x, hv.x), gv.x);
                    s = fma2(mul2(gaP.y, hv.y), gv.y, s);
                    float2 sv = upk(s);
                    float term = sv.x + sv.y;
                    #pragma unroll
                    for (int o=16;o>0;o>>=1)
                        term += __shfl_xor_sync(0xffffffffu, term, o);
                    if (lane == 0) gd_s[i*31+c] += term;
                }
            }
        }

        // GEMM3: gx += gh @ W0^T
        gemm128<true>(Ts, W0, Ws, tid, acc);
        if (tid < 256) {
            #pragma unroll
            for (int m=0;m<4;m++) {
                float* gp = &Xs[(r4+m)*FDIM + c4];
                gp[0] += acc[m][0]; gp[1] += acc[m][1];
                gp[2] += acc[m][2]; gp[3] += acc[m][3];
            }
        }
    }
    __syncthreads();

    // =============== action ===============
    {
        float* gp  = Ws;
        float* nrm = Ws + 96;
        float* cf  = Ws + 128;
        if (tid < 96) gp[tid] = 0.f;
        __syncthreads();
        for (int el=tid; el<APM*31; el+=512) {
            int i = el / 31, slot2 = el - i*31;
            if (slot2 < cntI[i]) {
                int pk = __float_as_int(liI[el]);
                int j = pk >> 14;
                float rx = pos_s[j*3+0]-pos_s[i*3+0];
                float ry = pos_s[j*3+1]-pos_s[i*3+1];
                float rz = pos_s[j*3+2]-pos_s[i*3+2];
                float d = sqrtf(rx*rx+ry*ry+rz*rz + 1e-12f);
                float g = gd_s[el] / d;
                atomicAdd(&gp[j*3+0],  g*rx); atomicAdd(&gp[j*3+1],  g*ry);
                atomicAdd(&gp[j*3+2],  g*rz);
                atomicAdd(&gp[i*3+0], -g*rx); atomicAdd(&gp[i*3+1], -g*ry);
                atomicAdd(&gp[i*3+2], -g*rz);
            }
        }
        __syncthreads();
        if (tid < APM) {
            float ax = gp[tid*3+0], ay = gp[tid*3+1], az = gp[tid*3+2];
            nrm[tid] = sqrtf(ax*ax + ay*ay + az*az);
        }
        __syncthreads();
        if (tid == 0) {
            float mx = 0.f;
            #pragma unroll
            for (int a=0;a<APM;a++) mx = fmaxf(mx, nrm[a]);
            cf[0] = fminf(1.0f / fmaxf(mx, 1e-8f), 1.0f);
        }
        __syncthreads();
        float coef = cf[0];
        for (int t=tid; t<96; t+=512)
            out[(size_t)abase*3 + t] = -gp[t]*coef;
    }
}

// ---------------- host ----------------
static const int MEGA_SMEM = SM_FLOATS * 4;

extern "C" void kernel_launch(void* const* d_in, const int* in_sizes, int n_in,
                              void* d_out, int out_size)
{
    const float* positions = (const float*)d_in[0];
    const float* emb       = (const float*)d_in[1];
    const float* in2f_W    = (const float*)d_in[2];
    const float* filt_W1   = (const float*)d_in[3];
    const float* filt_b1   = (const float*)d_in[4];
    const float* filt_W2   = (const float*)d_in[5];
    const float* filt_b2   = (const float*)d_in[6];
    const float* f2_W1     = (const float*)d_in[7];
    const float* f2_b1     = (const float*)d_in[8];
    const float* f2_W2     = (const float*)d_in[9];
    const float* f2_b2     = (const float*)d_in[10];
    const float* aw_W1     = (const float*)d_in[11];
    const float* aw_b1     = (const float*)d_in[12];
    const float* aw_W2     = (const float*)d_in[13];
    const float* aw_b2     = (const float*)d_in[14];
    const int*   Z         = (const int*)d_in[15];
    float* out = (float*)d_out;

    float *p_h, *p_sig2, *p_tabW, *p_tabD, *p_FWn, *p_Gn;
    cudaGetSymbolAddress((void**)&p_h,     g_h);
    cudaGetSymbolAddress((void**)&p_sig2,  g_sig2);
    cudaGetSymbolAddress((void**)&p_tabW,  g_tabW);
    cudaGetSymbolAddress((void**)&p_tabD,  g_tabD);
    cudaGetSymbolAddress((void**)&p_FWn,   g_FWn);
    cudaGetSymbolAddress((void**)&p_Gn,    g_Gn);

    cudaFuncSetAttribute(mega_k, cudaFuncAttributeMaxDynamicSharedMemorySize,
                         MEGA_SMEM);

    table_k<<<dim3(TABN,3),128>>>(filt_W1, filt_b1, filt_W2, filt_b2,
                                  p_tabW, p_tabD);
    upsample_k<<<dim3(TABF,3),128>>>(p_tabW, p_tabD, p_FWn, p_Gn);
    mega_k<<<NMOL, 512, MEGA_SMEM>>>(
        positions, emb, Z, in2f_W,
        f2_W1, f2_b1, f2_W2, f2_b2,
        aw_W1, aw_b1, aw_W2, aw_b2,
        p_FWn, p_Gn, p_h, p_sig2, out);
}

// round 14
// speedup vs baseline: 1.1274x; 1.0016x over previous
#include <cuda_runtime.h>
#include <math.h>

// ---------------- problem constants ----------------
#define NATOMS 16384
#define NMOL   512
#define APM    32
#define FDIM   128
#define NRBF   20
#define FH     64
#define NLAY   3
#define PI_F   3.14159265358979f
#define CUT    5.0f
#define LOG2_F 0.6931471805599453f
#define TABN   1024
#define TABF   16384

static const size_t NF = (size_t)NATOMS * FDIM;

typedef unsigned long long ull;

// ---------------- scratch ----------------
__device__ __align__(16) float  g_h    [3 * NF];
__device__ __align__(16) float  g_sig2 [3 * NF];
__device__ __align__(16) float  g_tabW [3 * TABN * FDIM];
__device__ __align__(16) float  g_tabD [3 * TABN * FDIM];
__device__ __align__(16) float  g_FWn  [3 * (size_t)TABF * FDIM];  // fc*W, fine grid
__device__ __align__(16) float  g_Gn   [3 * (size_t)TABF * FDIM];  // fc*D+dfc*W

__device__ __forceinline__ float sspf(float v) {
    return fmaxf(v, 0.f) + log1pf(expf(-fabsf(v))) - LOG2_F;
}
__device__ __forceinline__ ull pk2(float x) {
    ull r; asm("mov.b64 %0, {%1, %1};" : "=l"(r) : "f"(x)); return r;
}
__device__ __forceinline__ ull fma2(ull a, ull b, ull c) {
    ull d; asm("fma.rn.f32x2 %0, %1, %2, %3;" : "=l"(d) : "l"(a), "l"(b), "l"(c)); return d;
}
__device__ __forceinline__ ull mul2(ull a, ull b) {
    ull d; asm("mul.rn.f32x2 %0, %1, %2;" : "=l"(d) : "l"(a), "l"(b)); return d;
}
__device__ __forceinline__ float2 upk(ull v) {
    float2 r; asm("mov.b64 {%0, %1}, %2;" : "=f"(r.x), "=f"(r.y) : "l"(v)); return r;
}

// ---------------- coarse table build: 8 points per block ----------------
__global__ __launch_bounds__(128) void table_k(
    const float* __restrict__ W1, const float* __restrict__ b1,
    const float* __restrict__ W2, const float* __restrict__ b2,
    float* __restrict__ tabW, float* __restrict__ tabD)
{
    const int tb = blockIdx.x;       // 0..TABN/8-1
    const int l  = blockIdx.y;
    const int f  = threadIdx.x;
    const float DELTA = CUT / (NRBF-1);
    const float CO = -0.5f / (DELTA*DELTA);

    __shared__ float rbf_s [8*NRBF];
    __shared__ float drbf_s[8*NRBF];
    __shared__ float t1_s [FDIM*8];   // [c][pt]
    __shared__ float dt1_s[FDIM*8];

    for (int t = f; t < 8*NRBF; t += 128) {
        int pt = t / NRBF, k = t % NRBF;
        float d = (tb*8 + pt) * (CUT/(float)(TABN-1));
        float u = d - k*DELTA;
        float g = expf(CO*u*u);
        rbf_s[t]  = g;
        drbf_s[t] = g * (2.f*CO*u);
    }
    __syncthreads();

    const float* W1l = W1 + (size_t)l*NRBF*FDIM;
    float p[8], dp[8];
    float bb1 = b1[l*FDIM + f];
    #pragma unroll
    for (int pt=0;pt<8;pt++) { p[pt]=bb1; dp[pt]=0.f; }
    #pragma unroll
    for (int k=0;k<NRBF;k++) {
        float w = W1l[k*FDIM + f];
        #pragma unroll
        for (int pt=0;pt<8;pt++) {
            p[pt]  = fmaf(rbf_s [pt*NRBF+k], w, p[pt]);
            dp[pt] = fmaf(drbf_s[pt*NRBF+k], w, dp[pt]);
        }
    }
    #pragma unroll
    for (int pt=0;pt<8;pt++) {
        float sg = 1.f/(1.f+expf(-p[pt]));
        t1_s [f*8+pt] = sspf(p[pt]);
        dt1_s[f*8+pt] = sg*dp[pt];
    }
    __syncthreads();

    const float* W2l = W2 + (size_t)l*FDIM*FDIM;
    float w[8], dw[8];
    float bb2 = b2[l*FDIM + f];
    #pragma unroll
    for (int pt=0;pt<8;pt++) { w[pt]=bb2; dw[pt]=0.f; }
    for (int c=0;c<FDIM;c++) {
        float wv = W2l[(size_t)c*FDIM + f];
        float4 ta = *(const float4*)&t1_s [c*8];
        float4 tb4= *(const float4*)&t1_s [c*8+4];
        float4 da = *(const float4*)&dt1_s[c*8];
        float4 db = *(const float4*)&dt1_s[c*8+4];
        w[0]=fmaf(ta.x,wv,w[0]); w[1]=fmaf(ta.y,wv,w[1]);
        w[2]=fmaf(ta.z,wv,w[2]); w[3]=fmaf(ta.w,wv,w[3]);
        w[4]=fmaf(tb4.x,wv,w[4]); w[5]=fmaf(tb4.y,wv,w[5]);
        w[6]=fmaf(tb4.z,wv,w[6]); w[7]=fmaf(tb4.w,wv,w[7]);
        dw[0]=fmaf(da.x,wv,dw[0]); dw[1]=fmaf(da.y,wv,dw[1]);
        dw[2]=fmaf(da.z,wv,dw[2]); dw[3]=fmaf(da.w,wv,dw[3]);
        dw[4]=fmaf(db.x,wv,dw[4]); dw[5]=fmaf(db.y,wv,dw[5]);
        dw[6]=fmaf(db.z,wv,dw[6]); dw[7]=fmaf(db.w,wv,dw[7]);
    }
    #pragma unroll
    for (int pt=0;pt<8;pt++) {
        size_t o = ((size_t)l*TABN + tb*8 + pt)*FDIM + f;
        tabW[o] = w[pt];
        tabD[o] = dw[pt];
    }
}

// ---------------- upsample to fine nearest-neighbor tables ----------------
__global__ __launch_bounds__(128) void upsample_k(
    const float* __restrict__ tabW, const float* __restrict__ tabD,
    float* __restrict__ FWn, float* __restrict__ Gn)
{
    const int T = blockIdx.x, l = blockIdx.y, f = threadIdx.x;
    const float dfine = T * (CUT/(float)(TABF-1));
    float x = dfine * ((float)(TABN-1)/CUT);
    int t0 = (int)x; if (t0 > TABN-2) t0 = TABN-2;
    float fr = x - (float)t0;
    size_t oc = ((size_t)l*TABN + t0)*FDIM + f;
    float w0 = tabW[oc], w1 = tabW[oc+FDIM];
    float d0 = tabD[oc], d1 = tabD[oc+FDIM];
    float w = fmaf(fr, w1-w0, w0);
    float dd = fmaf(fr, d1-d0, d0);
    float ang = PI_F * dfine * (1.f/CUT);
    float fc  = 0.5f*(cosf(ang)+1.f);
    float dfc = -(0.5f*PI_F/CUT)*sinf(ang);
    size_t of = ((size_t)l*TABF + T)*FDIM + f;
    FWn[of] = fc*w;
    Gn[of]  = fmaf(fc, dd, dfc*w);
}

// ---------------- GEMM: C(32x128) = A_s @ B, f32x2, K-split-2, 4x4 tiles ----
template<bool TRANSB>
__device__ __forceinline__ void ldW(float* Wd, const float* __restrict__ Bg,
                                    int k0, int tid)
{
    if (!TRANSB) {
        int row = tid>>5, c4 = (tid&31)<<2;
        *(float4*)&Wd[row*FDIM + c4] =
            *(const float4*)&Bg[(size_t)(k0+row)*FDIM + c4];
    } else {
        int c = tid>>2, kq = (tid&3)<<2;
        float4 w = *(const float4*)&Bg[(size_t)c*FDIM + k0 + kq];
        Wd[(kq+0)*FDIM + c] = w.x;
        Wd[(kq+1)*FDIM + c] = w.y;
        Wd[(kq+2)*FDIM + c] = w.z;
        Wd[(kq+3)*FDIM + c] = w.w;
    }
}

template<bool TRANSB>
__device__ __forceinline__ void gemm128(const float* __restrict__ A_s,
                                        const float* __restrict__ Bg,
                                        float* Ws, int tid, float out[4][4])
{
    const int kh = tid >> 8;
    const int t  = tid & 255;
    const int r4 = (t >> 5) << 2;
    const int c4 = (t & 31) << 2;
    ull acc[4][2] = {};
    ldW<TRANSB>(Ws, Bg, 0, tid);
    __syncthreads();
    for (int ch=0; ch<8; ch++) {
        const float* Wc = Ws + (ch&1)*2048;
        if (ch < 7) ldW<TRANSB>(Ws + ((ch+1)&1)*2048, Bg, (ch+1)*16, tid);
        if ((ch>>2) == kh) {
            const int k0 = ch*16;
            #pragma unroll
            for (int kk=0;kk<16;kk++) {
                ull a0 = pk2(A_s[(r4+0)*FDIM + k0+kk]);
                ull a1 = pk2(A_s[(r4+1)*FDIM + k0+kk]);
                ull a2 = pk2(A_s[(r4+2)*FDIM + k0+kk]);
                ull a3 = pk2(A_s[(r4+3)*FDIM + k0+kk]);
                ulonglong2 bp = *(const ulonglong2*)&Wc[kk*FDIM + c4];
                acc[0][0]=fma2(a0,bp.x,acc[0][0]); acc[0][1]=fma2(a0,bp.y,acc[0][1]);
                acc[1][0]=fma2(a1,bp.x,acc[1][0]); acc[1][1]=fma2(a1,bp.y,acc[1][1]);
                acc[2][0]=fma2(a2,bp.x,acc[2][0]); acc[2][1]=fma2(a2,bp.y,acc[2][1]);
                acc[3][0]=fma2(a3,bp.x,acc[3][0]); acc[3][1]=fma2(a3,bp.y,acc[3][1]);
            }
        }
        __syncthreads();
    }
    ull* buf = (ull*)Ws;
    if (kh == 1) {
        ull* bp = buf + t*8;
        #pragma unroll
        for (int m=0;m<4;m++) { bp[m*2]=acc[m][0]; bp[m*2+1]=acc[m][1]; }
    }
    __syncthreads();
    if (kh == 0) {
        const ull* bp = buf + t*8;
        #pragma unroll
        for (int m=0;m<4;m++) {
            float2 p0 = upk(acc[m][0]), q0 = upk(bp[m*2]);
            float2 p1 = upk(acc[m][1]), q1 = upk(bp[m*2+1]);
            out[m][0]=p0.x+q0.x; out[m][1]=p0.y+q0.y;
            out[m][2]=p1.x+q1.x; out[m][3]=p1.y+q1.y;
        }
    }
    __syncthreads();
}

// ---------------- smem pool (floats) ----------------
#define OFF_XS   0
#define OFF_HS   (OFF_XS + APM*FDIM)
#define OFF_AS   (OFF_HS + APM*FDIM)
#define OFF_TS   (OFF_AS + APM*FDIM)
#define OFF_WS   (OFF_TS + APM*FDIM)        // 2 x 2048 (also reduction buffer)
#define OFF_LI   (OFF_WS + 4096)            // float[APM*31]
#define OFF_LJ   (OFF_LI + APM*31)
#define OFF_GD   (OFF_LJ + APM*31)
#define OFF_POS  (OFF_GD + APM*31)
#define OFF_PIJ  (OFF_POS + 96)             // uint8 posIJ[32][32] = 256 floats
#define OFF_CNT  (OFF_PIJ + 256)            // int[64]
#define OFF_ES   (OFF_CNT + 64)
#define SM_FLOATS (OFF_ES + 32)

__global__ __launch_bounds__(512,2) void mega_k(
    const float* __restrict__ pos, const float* __restrict__ emb,
    const int* __restrict__ Z,
    const float* __restrict__ in2f_W,
    const float* __restrict__ f2_W1, const float* __restrict__ f2_b1,
    const float* __restrict__ f2_W2, const float* __restrict__ f2_b2,
    const float* __restrict__ aw_W1, const float* __restrict__ aw_b1,
    const float* __restrict__ aw_W2, const float* __restrict__ aw_b2,
    const float* __restrict__ FWng, const float* __restrict__ Gng,
    float* __restrict__ g_h_, float* __restrict__ g_sig2_,
    float* __restrict__ out)
{
    extern __shared__ float sm[];
    float*  Xs    = sm + OFF_XS;
    float*  Hs    = sm + OFF_HS;
    float*  As    = sm + OFF_AS;
    float*  Ts    = sm + OFF_TS;
    float*  Ws    = sm + OFF_WS;
    float*  liI   = sm + OFF_LI;
    float*  liJ   = sm + OFF_LJ;
    float*  gd_s  = sm + OFF_GD;
    float*  pos_s = sm + OFF_POS;
    unsigned char* posIJ = (unsigned char*)(sm + OFF_PIJ);
    int*    cntI  = (int*)(sm + OFF_CNT);
    int*    cntJ  = cntI + 32;
    float*  es    = sm + OFF_ES;

    const int tid = threadIdx.x;
    const int mol = blockIdx.x;
    const int abase = mol*APM;

    const int rg = tid>>5, cg = tid&31;
    const int r0 = rg<<1, c0 = cg<<2;           // head-section mapping
    const int q  = tid & 255;
    const int r4 = (q>>5)<<2, c4 = (q&31)<<2;   // GEMM epilogue (tid<256)
    const int slot = tid>>5, lane = tid&31;     // edge loops: 16 warps x 32 lanes
    const int l4 = lane<<2;

    // ---------- P0: pos, gather x, zero gd ----------
    if (tid < 96) pos_s[tid] = pos[abase*3 + tid];
    for (int t=tid; t<APM*FDIM/4; t+=512) {
        int a = t>>5, f4 = (t&31)<<2;
        int z = Z[abase + a];
        *(float4*)&Xs[a*FDIM + f4] = *(const float4*)&emb[(size_t)z*FDIM + f4];
    }
    for (int t=tid; t<APM*31; t+=512) gd_s[t] = 0.f;
    __syncthreads();

    // ---------- P0b: compacted edge lists (phase A: by-i + posIJ) ----------
    if (tid < 32) {
        const int a = tid;      // i
        int count = 0;
        for (int c=0; c<31; c++) {
            int j = c + (c >= a ? 1 : 0);
            float rx = pos_s[j*3+0]-pos_s[a*3+0];
            float ry = pos_s[j*3+1]-pos_s[a*3+1];
            float rz = pos_s[j*3+2]-pos_s[a*3+2];
            float d = sqrtf(rx*rx+ry*ry+rz*rz + 1e-12f);
            if (d < CUT) {
                int T = (int)(d * ((float)(TABF-1)/CUT) + 0.5f);
                if (T > TABF-1) T = TABF-1;
                liI[a*31+count] = __int_as_float((j << 14) | T);
                posIJ[a*32 + j] = (unsigned char)count;
                count++;
            }
        }
        cntI[a] = count;
    }
    __syncthreads();
    // ---------- phase B: by-j with (i, slotI, T) packed ----------
    if (tid < 32) {
        const int a = tid;      // j
        int count = 0;
        for (int c=0; c<31; c++) {
            int i = c + (c >= a ? 1 : 0);
            float rx = pos_s[a*3+0]-pos_s[i*3+0];
            float ry = pos_s[a*3+1]-pos_s[i*3+1];
            float rz = pos_s[a*3+2]-pos_s[i*3+2];
            float d = sqrtf(rx*rx+ry*ry+rz*rz + 1e-12f);
            if (d < CUT) {
                int T = (int)(d * ((float)(TABF-1)/CUT) + 0.5f);
                if (T > TABF-1) T = TABF-1;
                int slotI = posIJ[i*32 + a];
                liJ[a*31+count] = __int_as_float((i << 19) | (slotI << 14) | T);
                count++;
            }
        }
        cntJ[a] = count;
    }
    // (gemm128's first __syncthreads publishes lists before any read)

    // =============== forward layers ===============
    for (int l = 0; l < NLAY; l++) {
        const float* W0 = in2f_W + (size_t)l*FDIM*FDIM;
        const float* W1 = f2_W1  + (size_t)l*FDIM*FDIM;
        const float* W2 = f2_W2  + (size_t)l*FDIM*FDIM;
        const float* FWl = FWng + (size_t)l*TABF*FDIM;
        float* s_g = g_sig2_ + (size_t)l*NF;
        float* h_g = g_h_ + (size_t)l*NF;

        float acc[4][4];
        // GEMM1: h = x @ W0 -> Hs (+global for l<2)
        gemm128<false>(Xs, W0, Ws, tid, acc);
        if (tid < 256) {
            #pragma unroll
            for (int m=0;m<4;m++) {
                float4 v = make_float4(acc[m][0],acc[m][1],acc[m][2],acc[m][3]);
                *(float4*)&Hs[(r4+m)*FDIM + c4] = v;
                if (l < 2)
                    *(float4*)&h_g[(size_t)(abase+r4+m)*FDIM + c4] = v;
            }
        }
        __syncthreads();

        // agg: As[i] = sum_j h[j] .* FW(d_ij), lane owns features 4l..4l+3
        #pragma unroll
        for (int it=0; it<2; it++) {
            int i = it*16 + slot;
            int cnt = cntI[i];
            ull a0=0ull, a1=0ull;
            for (int c=0;c<cnt;c++) {
                int pk = __float_as_int(liI[i*31+c]);
                int j = pk >> 14;
                int T = pk & 16383;
                ulonglong2 w = *(const ulonglong2*)&FWl[(size_t)T*FDIM + l4];
                ulonglong2 h = *(const ulonglong2*)&Hs[j*FDIM + l4];
                a0 = fma2(h.x, w.x, a0);
                a1 = fma2(h.y, w.y, a1);
            }
            ulonglong2 r; r.x=a0; r.y=a1;
            *(ulonglong2*)&As[i*FDIM + l4] = r;
        }

        // GEMM2: pre = agg@W1 + b1; sig2->global; t2=ssp->Ts
        gemm128<false>(As, W1, Ws, tid, acc);
        if (tid < 256) {
            float4 b1v = *(const float4*)&f2_b1[l*FDIM + c4];
            float bb[4]={b1v.x,b1v.y,b1v.z,b1v.w};
            #pragma unroll
            for (int m=0;m<4;m++) {
                float sg4[4];
                #pragma unroll
                for (int n=0;n<4;n++) {
                    float pre = acc[m][n] + bb[n];
                    sg4[n] = 1.f/(1.f+expf(-pre));
                    Ts[(r4+m)*FDIM + c4 + n] = sspf(pre);
                }
                *(float4*)&s_g[(size_t)(abase+r4+m)*FDIM + c4] =
                    make_float4(sg4[0],sg4[1],sg4[2],sg4[3]);
            }
        }

        // GEMM3: x += t2@W2 + b2
        gemm128<false>(Ts, W2, Ws, tid, acc);
        if (tid < 256) {
            float4 b2v = *(const float4*)&f2_b2[l*FDIM + c4];
            #pragma unroll
            for (int m=0;m<4;m++) {
                float* xp = &Xs[(r4+m)*FDIM + c4];
                xp[0] += acc[m][0] + b2v.x;
                xp[1] += acc[m][1] + b2v.y;
                xp[2] += acc[m][2] + b2v.z;
                xp[3] += acc[m][3] + b2v.w;
            }
        }
    }

    // =============== head: fwd + bwd ===============
    {
        if (tid < APM) es[tid] = 0.f;
        const int hc0 = cg<<1;
        float acc[2][2] = {};
        for (int k0=0;k0<FDIM;k0+=16) {
            __syncthreads();
            if (tid < 256) {
                int row = tid>>4, cc = (tid&15)<<2;
                *(float4*)&Ws[row*FH + cc] =
                    *(const float4*)&aw_W1[(size_t)(k0+row)*FH + cc];
            }
            __syncthreads();
            #pragma unroll
            for (int kk=0;kk<16;kk++) {
                float a0 = Xs[r0*FDIM + k0+kk];
                float a1 = Xs[(r0+1)*FDIM + k0+kk];
                float2 b = *(float2*)&Ws[kk*FH + hc0];
                acc[0][0]=fmaf(a0,b.x,acc[0][0]); acc[0][1]=fmaf(a0,b.y,acc[0][1]);
                acc[1][0]=fmaf(a1,b.x,acc[1][0]); acc[1][1]=fmaf(a1,b.y,acc[1][1]);
            }
        }
        float2 b1v = *(const float2*)&aw_b1[hc0];
        float2 w2v = *(const float2*)&aw_W2[hc0];
        float ep[2];
        #pragma unroll
        for (int m=0;m<2;m++) {
            float pre0 = acc[m][0] + b1v.x;
            float pre1 = acc[m][1] + b1v.y;
            float sg0 = 1.f/(1.f+expf(-pre0));
            float sg1 = 1.f/(1.f+expf(-pre1));
            ep[m] = sspf(pre0)*w2v.x + sspf(pre1)*w2v.y;
            Ts[(r0+m)*FH + hc0 + 0] = sg0*w2v.x;
            Ts[(r0+m)*FH + hc0 + 1] = sg1*w2v.y;
        }
        #pragma unroll
        for (int o=16;o>0;o>>=1) {
            ep[0] += __shfl_xor_sync(0xffffffffu, ep[0], o);
            ep[1] += __shfl_xor_sync(0xffffffffu, ep[1], o);
        }
        if (cg == 0) { es[r0] = ep[0]; es[r0+1] = ep[1]; }
        __syncthreads();
        if (tid == 0) {
            float s = APM * aw_b2[0];
            #pragma unroll
            for (int a=0;a<APM;a++) s += es[a];
            out[(size_t)3*NATOMS + mol] = s;
        }
        // GEMM2h: gx = gp @ aw_W1^T -> Xs
        float acc2[2][4] = {};
        for (int k0=0;k0<FH;k0+=16) {
            __syncthreads();
            {
                int f = tid>>2, kq = (tid&3)<<2;
                float4 w = *(const float4*)&aw_W1[(size_t)f*FH + k0 + kq];
                Ws[(kq+0)*FDIM + f] = w.x;
                Ws[(kq+1)*FDIM + f] = w.y;
                Ws[(kq+2)*FDIM + f] = w.z;
                Ws[(kq+3)*FDIM + f] = w.w;
            }
            __syncthreads();
            #pragma unroll
            for (int kk=0;kk<16;kk++) {
                float a0 = Ts[r0*FH + k0+kk];
                float a1 = Ts[(r0+1)*FH + k0+kk];
                float4 b = *(float4*)&Ws[kk*FDIM + c0];
                acc2[0][0]=fmaf(a0,b.x,acc2[0][0]); acc2[0][1]=fmaf(a0,b.y,acc2[0][1]);
                acc2[0][2]=fmaf(a0,b.z,acc2[0][2]); acc2[0][3]=fmaf(a0,b.w,acc2[0][3]);
                acc2[1][0]=fmaf(a1,b.x,acc2[1][0]); acc2[1][1]=fmaf(a1,b.y,acc2[1][1]);
                acc2[1][2]=fmaf(a1,b.z,acc2[1][2]); acc2[1][3]=fmaf(a1,b.w,acc2[1][3]);
            }
        }
        __syncthreads();
        #pragma unroll
        for (int m=0;m<2;m++)
            *(float4*)&Xs[(r0+m)*FDIM + c0] =
                make_float4(acc2[m][0],acc2[m][1],acc2[m][2],acc2[m][3]);
    }

    // =============== backward layers ===============
    for (int l = NLAY-1; l >= 0; l--) {
        const float* W0 = in2f_W + (size_t)l*FDIM*FDIM;
        const float* W1 = f2_W1  + (size_t)l*FDIM*FDIM;
        const float* W2 = f2_W2  + (size_t)l*FDIM*FDIM;
        const float* FWl = FWng + (size_t)l*TABF*FDIM;
        const float* Gl  = Gng  + (size_t)l*TABF*FDIM;
        const float* s_g = g_sig2_ + (size_t)l*NF;
        const float* h_g = g_h_ + (size_t)l*NF;

        if (l < 2) {   // Hs for l==2 persists from forward
            for (int t=tid; t<APM*FDIM/4; t+=512) {
                int a = t>>5, f4 = (t&31)<<2;
                *(float4*)&Hs[a*FDIM + f4] =
                    *(const float4*)&h_g[(size_t)(abase+a)*FDIM + f4];
            }
        }

        float acc[4][4];
        // GEMM1: gpre2 = (gx @ W2^T)*sig2 -> Ts
        gemm128<true>(Xs, W2, Ws, tid, acc);
        if (tid < 256) {
            #pragma unroll
            for (int m=0;m<4;m++) {
                float4 s4 = *(const float4*)&s_g[(size_t)(abase+r4+m)*FDIM + c4];
                Ts[(r4+m)*FDIM + c4 + 0] = acc[m][0]*s4.x;
                Ts[(r4+m)*FDIM + c4 + 1] = acc[m][1]*s4.y;
                Ts[(r4+m)*FDIM + c4 + 2] = acc[m][2]*s4.z;
                Ts[(r4+m)*FDIM + c4 + 3] = acc[m][3]*s4.w;
            }
        }

        // GEMM2: ga = gpre2 @ W1^T -> As
        gemm128<true>(Ts, W1, Ws, tid, acc);
        if (tid < 256) {
            #pragma unroll
            for (int m=0;m<4;m++)
                *(float4*)&As[(r4+m)*FDIM + c4] =
                    make_float4(acc[m][0],acc[m][1],acc[m][2],acc[m][3]);
        }
        __syncthreads();

        // fused gh + gd phase: warp per j-row
        //   gh[j] = sum_i ga[i] .* FW(d_ij) -> Ts
        //   gd[(i,j)] += sum_f ga[i,f]*h[j,f]*G(d_ij)[f]
        #pragma unroll
        for (int it=0; it<2; it++) {
            int j = it*16 + slot;
            int cnt = cntJ[j];
            ulonglong2 hj = *(const ulonglong2*)&Hs[j*FDIM + l4];
            ull a0=0ull, a1=0ull;
            for (int c=0;c<cnt;c++) {
                int pk = __float_as_int(liJ[j*31+c]);
                int i = pk >> 19;
                int slotI = (pk >> 14) & 31;
                int T = pk & 16383;
                ulonglong2 w  = *(const ulonglong2*)&FWl[(size_t)T*FDIM + l4];
                ulonglong2 gv = *(const ulonglong2*)&Gl[(size_t)T*FDIM + l4];
                ulonglong2 ga = *(const ulonglong2*)&As[i*FDIM + l4];
                a0 = fma2(ga.x, w.x, a0);
                a1 = fma2(ga.y, w.y, a1);
                ull s = mul2(mul2(ga.x, hj.x), gv.x);
                s = fma2(mul2(ga.y, hj.y), gv.y, s);
                float2 sv = upk(s);
                float term = sv.x + sv.y;
                #pragma unroll
                for (int o=16;o>0;o>>=1)
                    term += __shfl_xor_sync(0xffffffffu, term, o);
                if (lane == 0) gd_s[i*31+slotI] += term;
            }
            ulonglong2 r; r.x=a0; r.y=a1;
            *(ulonglong2*)&Ts[j*FDIM + l4] = r;
        }

        // GEMM3: gx += gh @ W0^T
        gemm128<true>(Ts, W0, Ws, tid, acc);
        if (tid < 256) {
            #pragma unroll
            for (int m=0;m<4;m++) {
                float* gp = &Xs[(r4+m)*FDIM + c4];
                gp[0] += acc[m][0]; gp[1] += acc[m][1];
                gp[2] += acc[m][2]; gp[3] += acc[m][3];
            }
        }
    }
    __syncthreads();

    // =============== action ===============
    {
        float* gp  = Ws;
        float* nrm = Ws + 96;
        float* cf  = Ws + 128;
        if (tid < 96) gp[tid] = 0.f;
        __syncthreads();
        for (int el=tid; el<APM*31; el+=512) {
            int i = el / 31, slot2 = el - i*31;
            if (slot2 < cntI[i]) {
                int pk = __float_as_int(liI[el]);
                int j = pk >> 14;
                float rx = pos_s[j*3+0]-pos_s[i*3+0];
                float ry = pos_s[j*3+1]-pos_s[i*3+1];
                float rz = pos_s[j*3+2]-pos_s[i*3+2];
                float d = sqrtf(rx*rx+ry*ry+rz*rz + 1e-12f);
                float g = gd_s[el] / d;
                atomicAdd(&gp[j*3+0],  g*rx); atomicAdd(&gp[j*3+1],  g*ry);
                atomicAdd(&gp[j*3+2],  g*rz);
                atomicAdd(&gp[i*3+0], -g*rx); atomicAdd(&gp[i*3+1], -g*ry);
                atomicAdd(&gp[i*3+2], -g*rz);
            }
        }
        __syncthreads();
        if (tid < APM) {
            float ax = gp[tid*3+0], ay = gp[tid*3+1], az = gp[tid*3+2];
            nrm[tid] = sqrtf(ax*ax + ay*ay + az*az);
        }
        __syncthreads();
        if (tid == 0) {
            float mx = 0.f;
            #pragma unroll
            for (int a=0;a<APM;a++) mx = fmaxf(mx, nrm[a]);
            cf[0] = fminf(1.0f / fmaxf(mx, 1e-8f), 1.0f);
        }
        __syncthreads();
        float coef = cf[0];
        for (int t=tid; t<96; t+=512)
            out[(size_t)abase*3 + t] = -gp[t]*coef;
    }
}

// ---------------- host ----------------
static const int MEGA_SMEM = SM_FLOATS * 4;

extern "C" void kernel_launch(void* const* d_in, const int* in_sizes, int n_in,
                              void* d_out, int out_size)
{
    const float* positions = (const float*)d_in[0];
    const float* emb       = (const float*)d_in[1];
    const float* in2f_W    = (const float*)d_in[2];
    const float* filt_W1   = (const float*)d_in[3];
    const float* filt_b1   = (const float*)d_in[4];
    const float* filt_W2   = (const float*)d_in[5];
    const float* filt_b2   = (const float*)d_in[6];
    const float* f2_W1     = (const float*)d_in[7];
    const float* f2_b1     = (const float*)d_in[8];
    const float* f2_W2     = (const float*)d_in[9];
    const float* f2_b2     = (const float*)d_in[10];
    const float* aw_W1     = (const float*)d_in[11];
    const float* aw_b1     = (const float*)d_in[12];
    const float* aw_W2     = (const float*)d_in[13];
    const float* aw_b2     = (const float*)d_in[14];
    const int*   Z         = (const int*)d_in[15];
    float* out = (float*)d_out;

    float *p_h, *p_sig2, *p_tabW, *p_tabD, *p_FWn, *p_Gn;
    cudaGetSymbolAddress((void**)&p_h,     g_h);
    cudaGetSymbolAddress((void**)&p_sig2,  g_sig2);
    cudaGetSymbolAddress((void**)&p_tabW,  g_tabW);
    cudaGetSymbolAddress((void**)&p_tabD,  g_tabD);
    cudaGetSymbolAddress((void**)&p_FWn,   g_FWn);
    cudaGetSymbolAddress((void**)&p_Gn,    g_Gn);

    cudaFuncSetAttribute(mega_k, cudaFuncAttributeMaxDynamicSharedMemorySize,
                         MEGA_SMEM);

    table_k<<<dim3(TABN/8,3),128>>>(filt_W1, filt_b1, filt_W2, filt_b2,
                                    p_tabW, p_tabD);
    upsample_k<<<dim3(TABF,3),128>>>(p_tabW, p_tabD, p_FWn, p_Gn);
    mega_k<<<NMOL, 512, MEGA_SMEM>>>(
        positions, emb, Z, in2f_W,
        f2_W1, f2_b1, f2_W2, f2_b2,
        aw_W1, aw_b1, aw_W2, aw_b2,
        p_FWn, p_Gn, p_h, p_sig2, out);
}

// round 15
// speedup vs baseline: 1.1353x; 1.0070x over previous
#include <cuda_runtime.h>
#include <math.h>

// ---------------- problem constants ----------------
#define NATOMS 16384
#define NMOL   512
#define APM    32
#define FDIM   128
#define NRBF   20
#define FH     64
#define NLAY   3
#define PI_F   3.14159265358979f
#define CUT    5.0f
#define LOG2_F 0.6931471805599453f
#define TABN   1024
#define TABF   16384

static const size_t NF = (size_t)NATOMS * FDIM;

typedef unsigned long long ull;

// ---------------- scratch ----------------
__device__ __align__(16) float  g_h    [3 * NF];
__device__ __align__(16) float  g_sig2 [3 * NF];
__device__ __align__(16) float  g_tabW [3 * TABN * FDIM];
__device__ __align__(16) float  g_tabD [3 * TABN * FDIM];
__device__ __align__(16) float  g_FWn  [3 * (size_t)TABF * FDIM];  // fc*W, fine grid
__device__ __align__(16) float  g_Gn   [3 * (size_t)TABF * FDIM];  // fc*D+dfc*W

__device__ __forceinline__ float sspf(float v) {
    return fmaxf(v, 0.f) + log1pf(expf(-fabsf(v))) - LOG2_F;
}
__device__ __forceinline__ ull pk2(float x) {
    ull r; asm("mov.b64 %0, {%1, %1};" : "=l"(r) : "f"(x)); return r;
}
__device__ __forceinline__ ull fma2(ull a, ull b, ull c) {
    ull d; asm("fma.rn.f32x2 %0, %1, %2, %3;" : "=l"(d) : "l"(a), "l"(b), "l"(c)); return d;
}
__device__ __forceinline__ ull mul2(ull a, ull b) {
    ull d; asm("mul.rn.f32x2 %0, %1, %2;" : "=l"(d) : "l"(a), "l"(b)); return d;
}
__device__ __forceinline__ float2 upk(ull v) {
    float2 r; asm("mov.b64 {%0, %1}, %2;" : "=f"(r.x), "=f"(r.y) : "l"(v)); return r;
}

// ---------------- coarse table build: 8 points per block ----------------
__global__ __launch_bounds__(128) void table_k(
    const float* __restrict__ W1, const float* __restrict__ b1,
    const float* __restrict__ W2, const float* __restrict__ b2,
    float* __restrict__ tabW, float* __restrict__ tabD)
{
    const int tb = blockIdx.x;
    const int l  = blockIdx.y;
    const int f  = threadIdx.x;
    const float DELTA = CUT / (NRBF-1);
    const float CO = -0.5f / (DELTA*DELTA);

    __shared__ float rbf_s [8*NRBF];
    __shared__ float drbf_s[8*NRBF];
    __shared__ float t1_s [FDIM*8];
    __shared__ float dt1_s[FDIM*8];

    for (int t = f; t < 8*NRBF; t += 128) {
        int pt = t / NRBF, k = t % NRBF;
        float d = (tb*8 + pt) * (CUT/(float)(TABN-1));
        float u = d - k*DELTA;
        float g = expf(CO*u*u);
        rbf_s[t]  = g;
        drbf_s[t] = g * (2.f*CO*u);
    }
    __syncthreads();

    const float* W1l = W1 + (size_t)l*NRBF*FDIM;
    float p[8], dp[8];
    float bb1 = b1[l*FDIM + f];
    #pragma unroll
    for (int pt=0;pt<8;pt++) { p[pt]=bb1; dp[pt]=0.f; }
    #pragma unroll
    for (int k=0;k<NRBF;k++) {
        float w = W1l[k*FDIM + f];
        #pragma unroll
        for (int pt=0;pt<8;pt++) {
            p[pt]  = fmaf(rbf_s [pt*NRBF+k], w, p[pt]);
            dp[pt] = fmaf(drbf_s[pt*NRBF+k], w, dp[pt]);
        }
    }
    #pragma unroll
    for (int pt=0;pt<8;pt++) {
        float sg = 1.f/(1.f+expf(-p[pt]));
        t1_s [f*8+pt] = sspf(p[pt]);
        dt1_s[f*8+pt] = sg*dp[pt];
    }
    __syncthreads();

    const float* W2l = W2 + (size_t)l*FDIM*FDIM;
    float w[8], dw[8];
    float bb2 = b2[l*FDIM + f];
    #pragma unroll
    for (int pt=0;pt<8;pt++) { w[pt]=bb2; dw[pt]=0.f; }
    for (int c=0;c<FDIM;c++) {
        float wv = W2l[(size_t)c*FDIM + f];
        float4 ta = *(const float4*)&t1_s [c*8];
        float4 tb4= *(const float4*)&t1_s [c*8+4];
        float4 da = *(const float4*)&dt1_s[c*8];
        float4 db = *(const float4*)&dt1_s[c*8+4];
        w[0]=fmaf(ta.x,wv,w[0]); w[1]=fmaf(ta.y,wv,w[1]);
        w[2]=fmaf(ta.z,wv,w[2]); w[3]=fmaf(ta.w,wv,w[3]);
        w[4]=fmaf(tb4.x,wv,w[4]); w[5]=fmaf(tb4.y,wv,w[5]);
        w[6]=fmaf(tb4.z,wv,w[6]); w[7]=fmaf(tb4.w,wv,w[7]);
        dw[0]=fmaf(da.x,wv,dw[0]); dw[1]=fmaf(da.y,wv,dw[1]);
        dw[2]=fmaf(da.z,wv,dw[2]); dw[3]=fmaf(da.w,wv,dw[3]);
        dw[4]=fmaf(db.x,wv,dw[4]); dw[5]=fmaf(db.y,wv,dw[5]);
        dw[6]=fmaf(db.z,wv,dw[6]); dw[7]=fmaf(db.w,wv,dw[7]);
    }
    #pragma unroll
    for (int pt=0;pt<8;pt++) {
        size_t o = ((size_t)l*TABN + tb*8 + pt)*FDIM + f;
        tabW[o] = w[pt];
        tabD[o] = dw[pt];
    }
}

// ---------------- upsample to fine nearest-neighbor tables ----------------
__global__ __launch_bounds__(128) void upsample_k(
    const float* __restrict__ tabW, const float* __restrict__ tabD,
    float* __restrict__ FWn, float* __restrict__ Gn)
{
    const int T = blockIdx.x, l = blockIdx.y, f = threadIdx.x;
    const float dfine = T * (CUT/(float)(TABF-1));
    float x = dfine * ((float)(TABN-1)/CUT);
    int t0 = (int)x; if (t0 > TABN-2) t0 = TABN-2;
    float fr = x - (float)t0;
    size_t oc = ((size_t)l*TABN + t0)*FDIM + f;
    float w0 = tabW[oc], w1 = tabW[oc+FDIM];
    float d0 = tabD[oc], d1 = tabD[oc+FDIM];
    float w = fmaf(fr, w1-w0, w0);
    float dd = fmaf(fr, d1-d0, d0);
    float ang = PI_F * dfine * (1.f/CUT);
    float fc  = 0.5f*(cosf(ang)+1.f);
    float dfc = -(0.5f*PI_F/CUT)*sinf(ang);
    size_t of = ((size_t)l*TABF + T)*FDIM + f;
    FWn[of] = fc*w;
    Gn[of]  = fmaf(fc, dd, dfc*w);
}

// ---------------- GEMM: C(32x128) = A_s @ B, f32x2, K-split-2, 4x4 tiles ----
// A-operand loaded as float4 per 4k (1 broadcast LDS.128 instead of 4 scalars)
template<bool TRANSB>
__device__ __forceinline__ void ldW(float* Wd, const float* __restrict__ Bg,
                                    int k0, int tid)
{
    if (!TRANSB) {
        int row = tid>>5, c4 = (tid&31)<<2;
        *(float4*)&Wd[row*FDIM + c4] =
            *(const float4*)&Bg[(size_t)(k0+row)*FDIM + c4];
    } else {
        int c = tid>>2, kq = (tid&3)<<2;
        float4 w = *(const float4*)&Bg[(size_t)c*FDIM + k0 + kq];
        Wd[(kq+0)*FDIM + c] = w.x;
        Wd[(kq+1)*FDIM + c] = w.y;
        Wd[(kq+2)*FDIM + c] = w.z;
        Wd[(kq+3)*FDIM + c] = w.w;
    }
}

template<bool TRANSB>
__device__ __forceinline__ void gemm128(const float* __restrict__ A_s,
                                        const float* __restrict__ Bg,
                                        float* Ws, int tid, float out[4][4])
{
    const int kh = tid >> 8;
    const int t  = tid & 255;
    const int r4 = (t >> 5) << 2;
    const int c4 = (t & 31) << 2;
    ull acc[4][2] = {};
    ldW<TRANSB>(Ws, Bg, 0, tid);
    __syncthreads();
    for (int ch=0; ch<8; ch++) {
        const float* Wc = Ws + (ch&1)*2048;
        if (ch < 7) ldW<TRANSB>(Ws + ((ch+1)&1)*2048, Bg, (ch+1)*16, tid);
        if ((ch>>2) == kh) {
            const int k0 = ch*16;
            #pragma unroll
            for (int kq=0; kq<16; kq+=4) {
                float4 av0 = *(const float4*)&A_s[(r4+0)*FDIM + k0+kq];
                float4 av1 = *(const float4*)&A_s[(r4+1)*FDIM + k0+kq];
                float4 av2 = *(const float4*)&A_s[(r4+2)*FDIM + k0+kq];
                float4 av3 = *(const float4*)&A_s[(r4+3)*FDIM + k0+kq];
                const float* a0p = (const float*)&av0;
                const float* a1p = (const float*)&av1;
                const float* a2p = (const float*)&av2;
                const float* a3p = (const float*)&av3;
                #pragma unroll
                for (int kk=0;kk<4;kk++) {
                    ull a0 = pk2(a0p[kk]);
                    ull a1 = pk2(a1p[kk]);
                    ull a2 = pk2(a2p[kk]);
                    ull a3 = pk2(a3p[kk]);
                    ulonglong2 bp = *(const ulonglong2*)&Wc[(kq+kk)*FDIM + c4];
                    acc[0][0]=fma2(a0,bp.x,acc[0][0]); acc[0][1]=fma2(a0,bp.y,acc[0][1]);
                    acc[1][0]=fma2(a1,bp.x,acc[1][0]); acc[1][1]=fma2(a1,bp.y,acc[1][1]);
                    acc[2][0]=fma2(a2,bp.x,acc[2][0]); acc[2][1]=fma2(a2,bp.y,acc[2][1]);
                    acc[3][0]=fma2(a3,bp.x,acc[3][0]); acc[3][1]=fma2(a3,bp.y,acc[3][1]);
                }
            }
        }
        __syncthreads();
    }
    ull* buf = (ull*)Ws;
    if (kh == 1) {
        ull* bp = buf + t*8;
        #pragma unroll
        for (int m=0;m<4;m++) { bp[m*2]=acc[m][0]; bp[m*2+1]=acc[m][1]; }
    }
    __syncthreads();
    if (kh == 0) {
        const ull* bp = buf + t*8;
        #pragma unroll
        for (int m=0;m<4;m++) {
            float2 p0 = upk(acc[m][0]), q0 = upk(bp[m*2]);
            float2 p1 = upk(acc[m][1]), q1 = upk(bp[m*2+1]);
            out[m][0]=p0.x+q0.x; out[m][1]=p0.y+q0.y;
            out[m][2]=p1.x+q1.x; out[m][3]=p1.y+q1.y;
        }
    }
    __syncthreads();
}

// ---------------- smem pool (floats) ----------------
#define OFF_XS   0
#define OFF_HS   (OFF_XS + APM*FDIM)
#define OFF_AS   (OFF_HS + APM*FDIM)
#define OFF_TS   (OFF_AS + APM*FDIM)
#define OFF_WS   (OFF_TS + APM*FDIM)        // 2 x 2048 (also reduction buffer)
#define OFF_LI   (OFF_WS + 4096)            // float[APM*31]
#define OFF_LJ   (OFF_LI + APM*31)
#define OFF_GD   (OFF_LJ + APM*31)
#define OFF_POS  (OFF_GD + APM*31)
#define OFF_PIJ  (OFF_POS + 96)             // uint8 posIJ[32][32] = 256 floats
#define OFF_CNT  (OFF_PIJ + 256)            // int[64]
#define OFF_ES   (OFF_CNT + 64)
#define SM_FLOATS (OFF_ES + 32)

__global__ __launch_bounds__(512,2) void mega_k(
    const float* __restrict__ pos, const float* __restrict__ emb,
    const int* __restrict__ Z,
    const float* __restrict__ in2f_W,
    const float* __restrict__ f2_W1, const float* __restrict__ f2_b1,
    const float* __restrict__ f2_W2, const float* __restrict__ f2_b2,
    const float* __restrict__ aw_W1, const float* __restrict__ aw_b1,
    const float* __restrict__ aw_W2, const float* __restrict__ aw_b2,
    const float* __restrict__ FWng, const float* __restrict__ Gng,
    float* __restrict__ g_h_, float* __restrict__ g_sig2_,
    float* __restrict__ out)
{
    extern __shared__ float sm[];
    float*  Xs    = sm + OFF_XS;
    float*  Hs    = sm + OFF_HS;
    float*  As    = sm + OFF_AS;
    float*  Ts    = sm + OFF_TS;
    float*  Ws    = sm + OFF_WS;
    float*  liI   = sm + OFF_LI;
    float*  liJ   = sm + OFF_LJ;
    float*  gd_s  = sm + OFF_GD;
    float*  pos_s = sm + OFF_POS;
    unsigned char* posIJ = (unsigned char*)(sm + OFF_PIJ);
    int*    cntI  = (int*)(sm + OFF_CNT);
    int*    cntJ  = cntI + 32;
    float*  es    = sm + OFF_ES;

    const int tid = threadIdx.x;
    const int mol = blockIdx.x;
    const int abase = mol*APM;

    const int rg = tid>>5, cg = tid&31;
    const int r0 = rg<<1, c0 = cg<<2;           // head-section mapping
    const int q  = tid & 255;
    const int r4 = (q>>5)<<2, c4 = (q&31)<<2;   // GEMM epilogue (tid<256)
    const int slot = tid>>5, lane = tid&31;     // edge loops: 16 warps x 32 lanes
    const int l4 = lane<<2;

    // ---------- P0: pos, gather x, zero gd ----------
    if (tid < 96) pos_s[tid] = pos[abase*3 + tid];
    for (int t=tid; t<APM*FDIM/4; t+=512) {
        int a = t>>5, f4 = (t&31)<<2;
        int z = Z[abase + a];
        *(float4*)&Xs[a*FDIM + f4] = *(const float4*)&emb[(size_t)z*FDIM + f4];
    }
    for (int t=tid; t<APM*31; t+=512) gd_s[t] = 0.f;
    __syncthreads();

    // ---------- P0b: compacted edge lists (phase A: by-i + posIJ) ----------
    if (tid < 32) {
        const int a = tid;      // i
        int count = 0;
        for (int c=0; c<31; c++) {
            int j = c + (c >= a ? 1 : 0);
            float rx = pos_s[j*3+0]-pos_s[a*3+0];
            float ry = pos_s[j*3+1]-pos_s[a*3+1];
            float rz = pos_s[j*3+2]-pos_s[a*3+2];
            float d = sqrtf(rx*rx+ry*ry+rz*rz + 1e-12f);
            if (d < CUT) {
                int T = (int)(d * ((float)(TABF-1)/CUT) + 0.5f);
                if (T > TABF-1) T = TABF-1;
                liI[a*31+count] = __int_as_float((j << 14) | T);
                posIJ[a*32 + j] = (unsigned char)count;
                count++;
            }
        }
        cntI[a] = count;
    }
    __syncthreads();
    // ---------- phase B: by-j with (i, slotI, T) packed ----------
    if (tid < 32) {
        const int a = tid;      // j
        int count = 0;
        for (int c=0; c<31; c++) {
            int i = c + (c >= a ? 1 : 0);
            float rx = pos_s[a*3+0]-pos_s[i*3+0];
            float ry = pos_s[a*3+1]-pos_s[i*3+1];
            float rz = pos_s[a*3+2]-pos_s[i*3+2];
            float d = sqrtf(rx*rx+ry*ry+rz*rz + 1e-12f);
            if (d < CUT) {
                int T = (int)(d * ((float)(TABF-1)/CUT) + 0.5f);
                if (T > TABF-1) T = TABF-1;
                int slotI = posIJ[i*32 + a];
                liJ[a*31+count] = __int_as_float((i << 19) | (slotI << 14) | T);
                count++;
            }
        }
        cntJ[a] = count;
    }
    // (gemm128's first __syncthreads publishes lists before any read)

    // =============== forward layers ===============
    for (int l = 0; l < NLAY; l++) {
        const float* W0 = in2f_W + (size_t)l*FDIM*FDIM;
        const float* W1 = f2_W1  + (size_t)l*FDIM*FDIM;
        const float* W2 = f2_W2  + (size_t)l*FDIM*FDIM;
        const float* FWl = FWng + (size_t)l*TABF*FDIM;
        float* s_g = g_sig2_ + (size_t)l*NF;
        float* h_g = g_h_ + (size_t)l*NF;

        float acc[4][4];
        // GEMM1: h = x @ W0 -> Hs (+global for l<2)
        gemm128<false>(Xs, W0, Ws, tid, acc);
        if (tid < 256) {
            #pragma unroll
            for (int m=0;m<4;m++) {
                float4 v = make_float4(acc[m][0],acc[m][1],acc[m][2],acc[m][3]);
                *(float4*)&Hs[(r4+m)*FDIM + c4] = v;
                if (l < 2)
                    *(float4*)&h_g[(size_t)(abase+r4+m)*FDIM + c4] = v;
            }
        }
        __syncthreads();

        // agg: As[i] = sum_j h[j] .* FW(d_ij), lane owns features 4l..4l+3
        #pragma unroll
        for (int it=0; it<2; it++) {
            int i = it*16 + slot;
            int cnt = cntI[i];
            ull a0=0ull, a1=0ull;
            for (int c=0;c<cnt;c++) {
                int pk = __float_as_int(liI[i*31+c]);
                int j = pk >> 14;
                int T = pk & 16383;
                ulonglong2 w = *(const ulonglong2*)&FWl[(size_t)T*FDIM + l4];
                ulonglong2 h = *(const ulonglong2*)&Hs[j*FDIM + l4];
                a0 = fma2(h.x, w.x, a0);
                a1 = fma2(h.y, w.y, a1);
            }
            ulonglong2 r; r.x=a0; r.y=a1;
            *(ulonglong2*)&As[i*FDIM + l4] = r;
        }

        // GEMM2: pre = agg@W1 + b1; sig2->global; t2=ssp->Ts
        gemm128<false>(As, W1, Ws, tid, acc);
        if (tid < 256) {
            float4 b1v = *(const float4*)&f2_b1[l*FDIM + c4];
            float bb[4]={b1v.x,b1v.y,b1v.z,b1v.w};
            #pragma unroll
            for (int m=0;m<4;m++) {
                float sg4[4];
                #pragma unroll
                for (int n=0;n<4;n++) {
                    float pre = acc[m][n] + bb[n];
                    sg4[n] = 1.f/(1.f+expf(-pre));
                    Ts[(r4+m)*FDIM + c4 + n] = sspf(pre);
                }
                *(float4*)&s_g[(size_t)(abase+r4+m)*FDIM + c4] =
                    make_float4(sg4[0],sg4[1],sg4[2],sg4[3]);
            }
        }

        // GEMM3: x += t2@W2 + b2
        gemm128<false>(Ts, W2, Ws, tid, acc);
        if (tid < 256) {
            float4 b2v = *(const float4*)&f2_b2[l*FDIM + c4];
            #pragma unroll
            for (int m=0;m<4;m++) {
                float* xp = &Xs[(r4+m)*FDIM + c4];
                xp[0] += acc[m][0] + b2v.x;
                xp[1] += acc[m][1] + b2v.y;
                xp[2] += acc[m][2] + b2v.z;
                xp[3] += acc[m][3] + b2v.w;
            }
        }
    }

    // =============== head: fwd + bwd ===============
    {
        if (tid < APM) es[tid] = 0.f;
        const int hc0 = cg<<1;
        float acc[2][2] = {};
        for (int k0=0;k0<FDIM;k0+=16) {
            __syncthreads();
            if (tid < 256) {
                int row = tid>>4, cc = (tid&15)<<2;
                *(float4*)&Ws[row*FH + cc] =
                    *(const float4*)&aw_W1[(size_t)(k0+row)*FH + cc];
            }
            __syncthreads();
            #pragma unroll
            for (int kk=0;kk<16;kk++) {
                float a0 = Xs[r0*FDIM + k0+kk];
                float a1 = Xs[(r0+1)*FDIM + k0+kk];
                float2 b = *(float2*)&Ws[kk*FH + hc0];
                acc[0][0]=fmaf(a0,b.x,acc[0][0]); acc[0][1]=fmaf(a0,b.y,acc[0][1]);
                acc[1][0]=fmaf(a1,b.x,acc[1][0]); acc[1][1]=fmaf(a1,b.y,acc[1][1]);
            }
        }
        float2 b1v = *(const float2*)&aw_b1[hc0];
        float2 w2v = *(const float2*)&aw_W2[hc0];
        float ep[2];
        #pragma unroll
        for (int m=0;m<2;m++) {
            float pre0 = acc[m][0] + b1v.x;
            float pre1 = acc[m][1] + b1v.y;
            float sg0 = 1.f/(1.f+expf(-pre0));
            float sg1 = 1.f/(1.f+expf(-pre1));
            ep[m] = sspf(pre0)*w2v.x + sspf(pre1)*w2v.y;
            Ts[(r0+m)*FH + hc0 + 0] = sg0*w2v.x;
            Ts[(r0+m)*FH + hc0 + 1] = sg1*w2v.y;
        }
        #pragma unroll
        for (int o=16;o>0;o>>=1) {
            ep[0] += __shfl_xor_sync(0xffffffffu, ep[0], o);
            ep[1] += __shfl_xor_sync(0xffffffffu, ep[1], o);
        }
        if (cg == 0) { es[r0] = ep[0]; es[r0+1] = ep[1]; }
        __syncthreads();
        if (tid == 0) {
            float s = APM * aw_b2[0];
            #pragma unroll
            for (int a=0;a<APM;a++) s += es[a];
            out[(size_t)3*NATOMS + mol] = s;
        }
        // GEMM2h: gx = gp @ aw_W1^T -> Xs
        float acc2[2][4] = {};
        for (int k0=0;k0<FH;k0+=16) {
            __syncthreads();
            {
                int f = tid>>2, kq = (tid&3)<<2;
                float4 w = *(const float4*)&aw_W1[(size_t)f*FH + k0 + kq];
                Ws[(kq+0)*FDIM + f] = w.x;
                Ws[(kq+1)*FDIM + f] = w.y;
                Ws[(kq+2)*FDIM + f] = w.z;
                Ws[(kq+3)*FDIM + f] = w.w;
            }
            __syncthreads();
            #pragma unroll
            for (int kk=0;kk<16;kk++) {
                float a0 = Ts[r0*FH + k0+kk];
                float a1 = Ts[(r0+1)*FH + k0+kk];
                float4 b = *(float4*)&Ws[kk*FDIM + c0];
                acc2[0][0]=fmaf(a0,b.x,acc2[0][0]); acc2[0][1]=fmaf(a0,b.y,acc2[0][1]);
                acc2[0][2]=fmaf(a0,b.z,acc2[0][2]); acc2[0][3]=fmaf(a0,b.w,acc2[0][3]);
                acc2[1][0]=fmaf(a1,b.x,acc2[1][0]); acc2[1][1]=fmaf(a1,b.y,acc2[1][1]);
                acc2[1][2]=fmaf(a1,b.z,acc2[1][2]); acc2[1][3]=fmaf(a1,b.w,acc2[1][3]);
            }
        }
        __syncthreads();
        #pragma unroll
        for (int m=0;m<2;m++)
            *(float4*)&Xs[(r0+m)*FDIM + c0] =
                make_float4(acc2[m][0],acc2[m][1],acc2[m][2],acc2[m][3]);
    }

    // =============== backward layers ===============
    for (int l = NLAY-1; l >= 0; l--) {
        const float* W0 = in2f_W + (size_t)l*FDIM*FDIM;
        const float* W1 = f2_W1  + (size_t)l*FDIM*FDIM;
        const float* W2 = f2_W2  + (size_t)l*FDIM*FDIM;
        const float* FWl = FWng + (size_t)l*TABF*FDIM;
        const float* Gl  = Gng  + (size_t)l*TABF*FDIM;
        const float* s_g = g_sig2_ + (size_t)l*NF;
        const float* h_g = g_h_ + (size_t)l*NF;

        if (l < 2) {   // Hs for l==2 persists from forward
            for (int t=tid; t<APM*FDIM/4; t+=512) {
                int a = t>>5, f4 = (t&31)<<2;
                *(float4*)&Hs[a*FDIM + f4] =
                    *(const float4*)&h_g[(size_t)(abase+a)*FDIM + f4];
            }
        }

        float acc[4][4];
        // GEMM1: gpre2 = (gx @ W2^T)*sig2 -> Ts
        gemm128<true>(Xs, W2, Ws, tid, acc);
        if (tid < 256) {
            #pragma unroll
            for (int m=0;m<4;m++) {
                float4 s4 = *(const float4*)&s_g[(size_t)(abase+r4+m)*FDIM + c4];
                Ts[(r4+m)*FDIM + c4 + 0] = acc[m][0]*s4.x;
                Ts[(r4+m)*FDIM + c4 + 1] = acc[m][1]*s4.y;
                Ts[(r4+m)*FDIM + c4 + 2] = acc[m][2]*s4.z;
                Ts[(r4+m)*FDIM + c4 + 3] = acc[m][3]*s4.w;
            }
        }

        // GEMM2: ga = gpre2 @ W1^T -> As
        gemm128<true>(Ts, W1, Ws, tid, acc);
        if (tid < 256) {
            #pragma unroll
            for (int m=0;m<4;m++)
                *(float4*)&As[(r4+m)*FDIM + c4] =
                    make_float4(acc[m][0],acc[m][1],acc[m][2],acc[m][3]);
        }
        __syncthreads();

        // fused gh + gd phase: warp per j-row
        #pragma unroll
        for (int it=0; it<2; it++) {
            int j = it*16 + slot;
            int cnt = cntJ[j];
            ulonglong2 hj = *(const ulonglong2*)&Hs[j*FDIM + l4];
            ull a0=0ull, a1=0ull;
            for (int c=0;c<cnt;c++) {
                int pk = __float_as_int(liJ[j*31+c]);
                int i = pk >> 19;
                int slotI = (pk >> 14) & 31;
                int T = pk & 16383;
                ulonglong2 w  = *(const ulonglong2*)&FWl[(size_t)T*FDIM + l4];
                ulonglong2 gv = *(const ulonglong2*)&Gl[(size_t)T*FDIM + l4];
                ulonglong2 ga = *(const ulonglong2*)&As[i*FDIM + l4];
                a0 = fma2(ga.x, w.x, a0);
                a1 = fma2(ga.y, w.y, a1);
                ull s = mul2(mul2(ga.x, hj.x), gv.x);
                s = fma2(mul2(ga.y, hj.y), gv.y, s);
                float2 sv = upk(s);
                float term = sv.x + sv.y;
                #pragma unroll
                for (int o=16;o>0;o>>=1)
                    term += __shfl_xor_sync(0xffffffffu, term, o);
                if (lane == 0) gd_s[i*31+slotI] += term;
            }
            ulonglong2 r; r.x=a0; r.y=a1;
            *(ulonglong2*)&Ts[j*FDIM + l4] = r;
        }

        // GEMM3: gx += gh @ W0^T
        gemm128<true>(Ts, W0, Ws, tid, acc);
        if (tid < 256) {
            #pragma unroll
            for (int m=0;m<4;m++) {
                float* gp = &Xs[(r4+m)*FDIM + c4];
                gp[0] += acc[m][0]; gp[1] += acc[m][1];
                gp[2] += acc[m][2]; gp[3] += acc[m][3];
            }
        }
    }
    __syncthreads();

    // =============== action ===============
    {
        float* gp  = Ws;
        float* nrm = Ws + 96;
        float* cf  = Ws + 128;
        if (tid < 96) gp[tid] = 0.f;
        __syncthreads();
        for (int el=tid; el<APM*31; el+=512) {
            int i = el / 31, slot2 = el - i*31;
            if (slot2 < cntI[i]) {
                int pk = __float_as_int(liI[el]);
                int j = pk >> 14;
                float rx = pos_s[j*3+0]-pos_s[i*3+0];
                float ry = pos_s[j*3+1]-pos_s[i*3+1];
                float rz = pos_s[j*3+2]-pos_s[i*3+2];
                float d = sqrtf(rx*rx+ry*ry+rz*rz + 1e-12f);
                float g = gd_s[el] / d;
                atomicAdd(&gp[j*3+0],  g*rx); atomicAdd(&gp[j*3+1],  g*ry);
                atomicAdd(&gp[j*3+2],  g*rz);
                atomicAdd(&gp[i*3+0], -g*rx); atomicAdd(&gp[i*3+1], -g*ry);
                atomicAdd(&gp[i*3+2], -g*rz);
            }
        }
        __syncthreads();
        if (tid < APM) {
            float ax = gp[tid*3+0], ay = gp[tid*3+1], az = gp[tid*3+2];
            nrm[tid] = sqrtf(ax*ax + ay*ay + az*az);
        }
        __syncthreads();
        if (tid == 0) {
            float mx = 0.f;
            #pragma unroll
            for (int a=0;a<APM;a++) mx = fmaxf(mx, nrm[a]);
            cf[0] = fminf(1.0f / fmaxf(mx, 1e-8f), 1.0f);
        }
        __syncthreads();
        float coef = cf[0];
        for (int t=tid; t<96; t+=512)
            out[(size_t)abase*3 + t] = -gp[t]*coef;
    }
}

// ---------------- host ----------------
static const int MEGA_SMEM = SM_FLOATS * 4;

extern "C" void kernel_launch(void* const* d_in, const int* in_sizes, int n_in,
                              void* d_out, int out_size)
{
    const float* positions = (const float*)d_in[0];
    const float* emb       = (const float*)d_in[1];
    const float* in2f_W    = (const float*)d_in[2];
    const float* filt_W1   = (const float*)d_in[3];
    const float* filt_b1   = (const float*)d_in[4];
    const float* filt_W2   = (const float*)d_in[5];
    const float* filt_b2   = (const float*)d_in[6];
    const float* f2_W1     = (const float*)d_in[7];
    const float* f2_b1     = (const float*)d_in[8];
    const float* f2_W2     = (const float*)d_in[9];
    const float* f2_b2     = (const float*)d_in[10];
    const float* aw_W1     = (const float*)d_in[11];
    const float* aw_b1     = (const float*)d_in[12];
    const float* aw_W2     = (const float*)d_in[13];
    const float* aw_b2     = (const float*)d_in[14];
    const int*   Z         = (const int*)d_in[15];
    float* out = (float*)d_out;

    float *p_h, *p_sig2, *p_tabW, *p_tabD, *p_FWn, *p_Gn;
    cudaGetSymbolAddress((void**)&p_h,     g_h);
    cudaGetSymbolAddress((void**)&p_sig2,  g_sig2);
    cudaGetSymbolAddress((void**)&p_tabW,  g_tabW);
    cudaGetSymbolAddress((void**)&p_tabD,  g_tabD);
    cudaGetSymbolAddress((void**)&p_FWn,   g_FWn);
    cudaGetSymbolAddress((void**)&p_Gn,    g_Gn);

    cudaFuncSetAttribute(mega_k, cudaFuncAttributeMaxDynamicSharedMemorySize,
                         MEGA_SMEM);

    table_k<<<dim3(TABN/8,3),128>>>(filt_W1, filt_b1, filt_W2, filt_b2,
                                    p_tabW, p_tabD);
    upsample_k<<<dim3(TABF,3),128>>>(p_tabW, p_tabD, p_FWn, p_Gn);
    mega_k<<<NMOL, 512, MEGA_SMEM>>>(
        positions, emb, Z, in2f_W,
        f2_W1, f2_b1, f2_W2, f2_b2,
        aw_W1, aw_b1, aw_W2, aw_b2,
        p_FWn, p_Gn, p_h, p_sig2, out);
}

// round 16
// speedup vs baseline: 1.1589x; 1.0208x over previous
#include <cuda_runtime.h>
#include <math.h>

// ---------------- problem constants ----------------
#define NATOMS 16384
#define NMOL   512
#define APM    32
#define FDIM   128
#define NRBF   20
#define FH     64
#define NLAY   3
#define PI_F   3.14159265358979f
#define CUT    5.0f
#define LOG2_F 0.6931471805599453f
#define TABN   1024
#define TABF   16384

static const size_t NF = (size_t)NATOMS * FDIM;

typedef unsigned long long ull;

// ---------------- scratch ----------------
__device__ __align__(16) float  g_h    [3 * NF];
__device__ __align__(16) float  g_sig2 [3 * NF];
__device__ __align__(16) float  g_tabW [3 * TABN * FDIM];
__device__ __align__(16) float  g_tabD [3 * TABN * FDIM];
__device__ __align__(16) float  g_FWn  [3 * (size_t)TABF * FDIM];
__device__ __align__(16) float  g_Gn   [3 * (size_t)TABF * FDIM];

__device__ __forceinline__ float sspf(float v) {
    return fmaxf(v, 0.f) + log1pf(expf(-fabsf(v))) - LOG2_F;
}
__device__ __forceinline__ ull pk2(float x) {
    ull r; asm("mov.b64 %0, {%1, %1};" : "=l"(r) : "f"(x)); return r;
}
__device__ __forceinline__ ull pk2f(float x, float y) {
    ull r; asm("mov.b64 %0, {%1, %2};" : "=l"(r) : "f"(x), "f"(y)); return r;
}
__device__ __forceinline__ ull fma2(ull a, ull b, ull c) {
    ull d; asm("fma.rn.f32x2 %0, %1, %2, %3;" : "=l"(d) : "l"(a), "l"(b), "l"(c)); return d;
}
__device__ __forceinline__ ull mul2(ull a, ull b) {
    ull d; asm("mul.rn.f32x2 %0, %1, %2;" : "=l"(d) : "l"(a), "l"(b)); return d;
}
__device__ __forceinline__ ull add2(ull a, ull b) {
    ull d; asm("add.rn.f32x2 %0, %1, %2;" : "=l"(d) : "l"(a), "l"(b)); return d;
}
__device__ __forceinline__ float2 upk(ull v) {
    float2 r; asm("mov.b64 {%0, %1}, %2;" : "=f"(r.x), "=f"(r.y) : "l"(v)); return r;
}

// ---------------- coarse table build: 8 points per block ----------------
__global__ __launch_bounds__(128) void table_k(
    const float* __restrict__ W1, const float* __restrict__ b1,
    const float* __restrict__ W2, const float* __restrict__ b2,
    float* __restrict__ tabW, float* __restrict__ tabD)
{
    const int tb = blockIdx.x;
    const int l  = blockIdx.y;
    const int f  = threadIdx.x;
    const float DELTA = CUT / (NRBF-1);
    const float CO = -0.5f / (DELTA*DELTA);

    __shared__ float rbf_s [8*NRBF];
    __shared__ float drbf_s[8*NRBF];
    __shared__ float t1_s [FDIM*8];
    __shared__ float dt1_s[FDIM*8];

    for (int t = f; t < 8*NRBF; t += 128) {
        int pt = t / NRBF, k = t % NRBF;
        float d = (tb*8 + pt) * (CUT/(float)(TABN-1));
        float u = d - k*DELTA;
        float g = expf(CO*u*u);
        rbf_s[t]  = g;
        drbf_s[t] = g * (2.f*CO*u);
    }
    __syncthreads();

    const float* W1l = W1 + (size_t)l*NRBF*FDIM;
    float p[8], dp[8];
    float bb1 = b1[l*FDIM + f];
    #pragma unroll
    for (int pt=0;pt<8;pt++) { p[pt]=bb1; dp[pt]=0.f; }
    #pragma unroll
    for (int k=0;k<NRBF;k++) {
        float w = W1l[k*FDIM + f];
        #pragma unroll
        for (int pt=0;pt<8;pt++) {
            p[pt]  = fmaf(rbf_s [pt*NRBF+k], w, p[pt]);
            dp[pt] = fmaf(drbf_s[pt*NRBF+k], w, dp[pt]);
        }
    }
    #pragma unroll
    for (int pt=0;pt<8;pt++) {
        float sg = 1.f/(1.f+expf(-p[pt]));
        t1_s [f*8+pt] = sspf(p[pt]);
        dt1_s[f*8+pt] = sg*dp[pt];
    }
    __syncthreads();

    const float* W2l = W2 + (size_t)l*FDIM*FDIM;
    float w[8], dw[8];
    float bb2 = b2[l*FDIM + f];
    #pragma unroll
    for (int pt=0;pt<8;pt++) { w[pt]=bb2; dw[pt]=0.f; }
    for (int c=0;c<FDIM;c++) {
        float wv = W2l[(size_t)c*FDIM + f];
        float4 ta = *(const float4*)&t1_s [c*8];
        float4 tb4= *(const float4*)&t1_s [c*8+4];
        float4 da = *(const float4*)&dt1_s[c*8];
        float4 db = *(const float4*)&dt1_s[c*8+4];
        w[0]=fmaf(ta.x,wv,w[0]); w[1]=fmaf(ta.y,wv,w[1]);
        w[2]=fmaf(ta.z,wv,w[2]); w[3]=fmaf(ta.w,wv,w[3]);
        w[4]=fmaf(tb4.x,wv,w[4]); w[5]=fmaf(tb4.y,wv,w[5]);
        w[6]=fmaf(tb4.z,wv,w[6]); w[7]=fmaf(tb4.w,wv,w[7]);
        dw[0]=fmaf(da.x,wv,dw[0]); dw[1]=fmaf(da.y,wv,dw[1]);
        dw[2]=fmaf(da.z,wv,dw[2]); dw[3]=fmaf(da.w,wv,dw[3]);
        dw[4]=fmaf(db.x,wv,dw[4]); dw[5]=fmaf(db.y,wv,dw[5]);
        dw[6]=fmaf(db.z,wv,dw[6]); dw[7]=fmaf(db.w,wv,dw[7]);
    }
    #pragma unroll
    for (int pt=0;pt<8;pt++) {
        size_t o = ((size_t)l*TABN + tb*8 + pt)*FDIM + f;
        tabW[o] = w[pt];
        tabD[o] = dw[pt];
    }
}

// ---------------- upsample to fine nearest-neighbor tables ----------------
__global__ __launch_bounds__(128) void upsample_k(
    const float* __restrict__ tabW, const float* __restrict__ tabD,
    float* __restrict__ FWn, float* __restrict__ Gn)
{
    const int T = blockIdx.x, l = blockIdx.y, f = threadIdx.x;
    const float dfine = T * (CUT/(float)(TABF-1));
    float x = dfine * ((float)(TABN-1)/CUT);
    int t0 = (int)x; if (t0 > TABN-2) t0 = TABN-2;
    float fr = x - (float)t0;
    size_t oc = ((size_t)l*TABN + t0)*FDIM + f;
    float w0 = tabW[oc], w1 = tabW[oc+FDIM];
    float d0 = tabD[oc], d1 = tabD[oc+FDIM];
    float w = fmaf(fr, w1-w0, w0);
    float dd = fmaf(fr, d1-d0, d0);
    float ang = PI_F * dfine * (1.f/CUT);
    float fc  = 0.5f*(cosf(ang)+1.f);
    float dfc = -(0.5f*PI_F/CUT)*sinf(ang);
    size_t of = ((size_t)l*TABF + T)*FDIM + f;
    FWn[of] = fc*w;
    Gn[of]  = fmaf(fc, dd, dfc*w);
}

// ---------------- GEMM: C(32x128) = A_s @ B, f32x2, K-split-2, 4x4 tiles ----
template<bool TRANSB>
__device__ __forceinline__ void ldW(float* Wd, const float* __restrict__ Bg,
                                    int k0, int tid)
{
    if (!TRANSB) {
        int row = tid>>5, c4 = (tid&31)<<2;
        *(float4*)&Wd[row*FDIM + c4] =
            *(const float4*)&Bg[(size_t)(k0+row)*FDIM + c4];
    } else {
        int c = tid>>2, kq = (tid&3)<<2;
        float4 w = *(const float4*)&Bg[(size_t)c*FDIM + k0 + kq];
        Wd[(kq+0)*FDIM + c] = w.x;
        Wd[(kq+1)*FDIM + c] = w.y;
        Wd[(kq+2)*FDIM + c] = w.z;
        Wd[(kq+3)*FDIM + c] = w.w;
    }
}

template<bool TRANSB>
__device__ __forceinline__ void gemm128(const float* __restrict__ A_s,
                                        const float* __restrict__ Bg,
                                        float* Ws, int tid, float out[4][4])
{
    const int kh = tid >> 8;
    const int t  = tid & 255;
    const int r4 = (t >> 5) << 2;
    const int c4 = (t & 31) << 2;
    ull acc[4][2] = {};
    ldW<TRANSB>(Ws, Bg, 0, tid);
    __syncthreads();
    for (int ch=0; ch<8; ch++) {
        const float* Wc = Ws + (ch&1)*2048;
        if (ch < 7) ldW<TRANSB>(Ws + ((ch+1)&1)*2048, Bg, (ch+1)*16, tid);
        if ((ch>>2) == kh) {
            const int k0 = ch*16;
            #pragma unroll
            for (int kq=0; kq<16; kq+=4) {
                float4 av0 = *(const float4*)&A_s[(r4+0)*FDIM + k0+kq];
                float4 av1 = *(const float4*)&A_s[(r4+1)*FDIM + k0+kq];
                float4 av2 = *(const float4*)&A_s[(r4+2)*FDIM + k0+kq];
                float4 av3 = *(const float4*)&A_s[(r4+3)*FDIM + k0+kq];
                const float* a0p = (const float*)&av0;
                const float* a1p = (const float*)&av1;
                const float* a2p = (const float*)&av2;
                const float* a3p = (const float*)&av3;
                #pragma unroll
                for (int kk=0;kk<4;kk++) {
                    ull a0 = pk2(a0p[kk]);
                    ull a1 = pk2(a1p[kk]);
                    ull a2 = pk2(a2p[kk]);
                    ull a3 = pk2(a3p[kk]);
                    ulonglong2 bp = *(const ulonglong2*)&Wc[(kq+kk)*FDIM + c4];
                    acc[0][0]=fma2(a0,bp.x,acc[0][0]); acc[0][1]=fma2(a0,bp.y,acc[0][1]);
                    acc[1][0]=fma2(a1,bp.x,acc[1][0]); acc[1][1]=fma2(a1,bp.y,acc[1][1]);
                    acc[2][0]=fma2(a2,bp.x,acc[2][0]); acc[2][1]=fma2(a2,bp.y,acc[2][1]);
                    acc[3][0]=fma2(a3,bp.x,acc[3][0]); acc[3][1]=fma2(a3,bp.y,acc[3][1]);
                }
            }
        }
        __syncthreads();
    }
    ull* buf = (ull*)Ws;
    if (kh == 1) {
        ull* bp = buf + t*8;
        #pragma unroll
        for (int m=0;m<4;m++) { bp[m*2]=acc[m][0]; bp[m*2+1]=acc[m][1]; }
    }
    __syncthreads();
    if (kh == 0) {
        const ull* bp = buf + t*8;
        #pragma unroll
        for (int m=0;m<4;m++) {
            float2 p0 = upk(acc[m][0]), q0 = upk(bp[m*2]);
            float2 p1 = upk(acc[m][1]), q1 = upk(bp[m*2+1]);
            out[m][0]=p0.x+q0.x; out[m][1]=p0.y+q0.y;
            out[m][2]=p1.x+q1.x; out[m][3]=p1.y+q1.y;
        }
    }
    __syncthreads();
}

// ---------------- smem pool (floats) ----------------
#define OFF_XS   0
#define OFF_HS   (OFF_XS + APM*FDIM)
#define OFF_AS   (OFF_HS + APM*FDIM)
#define OFF_TS   (OFF_AS + APM*FDIM)
#define OFF_WS   (OFF_TS + APM*FDIM)
#define OFF_LI   (OFF_WS + 4096)
#define OFF_LJ   (OFF_LI + APM*31)
#define OFF_GD   (OFF_LJ + APM*31)
#define OFF_POS  (OFF_GD + APM*31)
#define OFF_PIJ  (OFF_POS + 96)
#define OFF_CNT  (OFF_PIJ + 256)
#define OFF_ES   (OFF_CNT + 64)
#define SM_FLOATS (OFF_ES + 32)

__global__ __launch_bounds__(512,2) void mega_k(
    const float* __restrict__ pos, const float* __restrict__ emb,
    const int* __restrict__ Z,
    const float* __restrict__ in2f_W,
    const float* __restrict__ f2_W1, const float* __restrict__ f2_b1,
    const float* __restrict__ f2_W2, const float* __restrict__ f2_b2,
    const float* __restrict__ aw_W1, const float* __restrict__ aw_b1,
    const float* __restrict__ aw_W2, const float* __restrict__ aw_b2,
    const float* __restrict__ FWng, const float* __restrict__ Gng,
    float* __restrict__ g_h_, float* __restrict__ g_sig2_,
    float* __restrict__ out)
{
    extern __shared__ float sm[];
    float*  Xs    = sm + OFF_XS;
    float*  Hs    = sm + OFF_HS;
    float*  As    = sm + OFF_AS;
    float*  Ts    = sm + OFF_TS;
    float*  Ws    = sm + OFF_WS;
    float*  liI   = sm + OFF_LI;
    float*  liJ   = sm + OFF_LJ;
    float*  gd_s  = sm + OFF_GD;
    float*  pos_s = sm + OFF_POS;
    unsigned char* posIJ = (unsigned char*)(sm + OFF_PIJ);
    int*    cntI  = (int*)(sm + OFF_CNT);
    int*    cntJ  = cntI + 32;
    float*  es    = sm + OFF_ES;

    const int tid = threadIdx.x;
    const int mol = blockIdx.x;
    const int abase = mol*APM;

    const int rg = tid>>5, cg = tid&31;
    const int r0 = rg<<1, c0 = cg<<2;
    const int q  = tid & 255;
    const int r4 = (q>>5)<<2, c4 = (q&31)<<2;
    const int slot = tid>>5, lane = tid&31;
    const int l4 = lane<<2;

    // ---------- P0 ----------
    if (tid < 96) pos_s[tid] = pos[abase*3 + tid];
    for (int t=tid; t<APM*FDIM/4; t+=512) {
        int a = t>>5, f4 = (t&31)<<2;
        int z = Z[abase + a];
        *(float4*)&Xs[a*FDIM + f4] = *(const float4*)&emb[(size_t)z*FDIM + f4];
    }
    for (int t=tid; t<APM*31; t+=512) gd_s[t] = 0.f;
    __syncthreads();

    // ---------- edge lists ----------
    if (tid < 32) {
        const int a = tid;
        int count = 0;
        for (int c=0; c<31; c++) {
            int j = c + (c >= a ? 1 : 0);
            float rx = pos_s[j*3+0]-pos_s[a*3+0];
            float ry = pos_s[j*3+1]-pos_s[a*3+1];
            float rz = pos_s[j*3+2]-pos_s[a*3+2];
            float d = sqrtf(rx*rx+ry*ry+rz*rz + 1e-12f);
            if (d < CUT) {
                int T = (int)(d * ((float)(TABF-1)/CUT) + 0.5f);
                if (T > TABF-1) T = TABF-1;
                liI[a*31+count] = __int_as_float((j << 14) | T);
                posIJ[a*32 + j] = (unsigned char)count;
                count++;
            }
        }
        cntI[a] = count;
    }
    __syncthreads();
    if (tid < 32) {
        const int a = tid;
        int count = 0;
        for (int c=0; c<31; c++) {
            int i = c + (c >= a ? 1 : 0);
            float rx = pos_s[a*3+0]-pos_s[i*3+0];
            float ry = pos_s[a*3+1]-pos_s[i*3+1];
            float rz = pos_s[a*3+2]-pos_s[i*3+2];
            float d = sqrtf(rx*rx+ry*ry+rz*rz + 1e-12f);
            if (d < CUT) {
                int T = (int)(d * ((float)(TABF-1)/CUT) + 0.5f);
                if (T > TABF-1) T = TABF-1;
                int slotI = posIJ[i*32 + a];
                liJ[a*31+count] = __int_as_float((i << 19) | (slotI << 14) | T);
                count++;
            }
        }
        cntJ[a] = count;
    }

    // =============== forward layers ===============
    for (int l = 0; l < NLAY; l++) {
        const float* W0 = in2f_W + (size_t)l*FDIM*FDIM;
        const float* W1 = f2_W1  + (size_t)l*FDIM*FDIM;
        const float* W2 = f2_W2  + (size_t)l*FDIM*FDIM;
        const float* FWl = FWng + (size_t)l*TABF*FDIM;
        float* s_g = g_sig2_ + (size_t)l*NF;
        float* h_g = g_h_ + (size_t)l*NF;

        float acc[4][4];
        gemm128<false>(Xs, W0, Ws, tid, acc);
        if (tid < 256) {
            #pragma unroll
            for (int m=0;m<4;m++) {
                float4 v = make_float4(acc[m][0],acc[m][1],acc[m][2],acc[m][3]);
                *(float4*)&Hs[(r4+m)*FDIM + c4] = v;
                if (l < 2)
                    *(float4*)&h_g[(size_t)(abase+r4+m)*FDIM + c4] = v;
            }
        }
        __syncthreads();

        // agg
        #pragma unroll
        for (int it=0; it<2; it++) {
            int i = it*16 + slot;
            int cnt = cntI[i];
            ull a0=0ull, a1=0ull;
            for (int c=0;c<cnt;c++) {
                int pk = __float_as_int(liI[i*31+c]);
                int j = pk >> 14;
                int T = pk & 16383;
                ulonglong2 w = *(const ulonglong2*)&FWl[(size_t)T*FDIM + l4];
                ulonglong2 h = *(const ulonglong2*)&Hs[j*FDIM + l4];
                a0 = fma2(h.x, w.x, a0);
                a1 = fma2(h.y, w.y, a1);
            }
            ulonglong2 r; r.x=a0; r.y=a1;
            *(ulonglong2*)&As[i*FDIM + l4] = r;
        }

        gemm128<false>(As, W1, Ws, tid, acc);
        if (tid < 256) {
            float4 b1v = *(const float4*)&f2_b1[l*FDIM + c4];
            float bb[4]={b1v.x,b1v.y,b1v.z,b1v.w};
            #pragma unroll
            for (int m=0;m<4;m++) {
                float sg4[4];
                #pragma unroll
                for (int n=0;n<4;n++) {
                    float pre = acc[m][n] + bb[n];
                    sg4[n] = 1.f/(1.f+expf(-pre));
                    Ts[(r4+m)*FDIM + c4 + n] = sspf(pre);
                }
                *(float4*)&s_g[(size_t)(abase+r4+m)*FDIM + c4] =
                    make_float4(sg4[0],sg4[1],sg4[2],sg4[3]);
            }
        }

        gemm128<false>(Ts, W2, Ws, tid, acc);
        if (tid < 256) {
            float4 b2v = *(const float4*)&f2_b2[l*FDIM + c4];
            #pragma unroll
            for (int m=0;m<4;m++) {
                float* xp = &Xs[(r4+m)*FDIM + c4];
                xp[0] += acc[m][0] + b2v.x;
                xp[1] += acc[m][1] + b2v.y;
                xp[2] += acc[m][2] + b2v.z;
                xp[3] += acc[m][3] + b2v.w;
            }
        }
    }

    // =============== head ===============
    {
        if (tid < APM) es[tid] = 0.f;
        const int hc0 = cg<<1;
        float acc[2][2] = {};
        for (int k0=0;k0<FDIM;k0+=16) {
            __syncthreads();
            if (tid < 256) {
                int row = tid>>4, cc = (tid&15)<<2;
                *(float4*)&Ws[row*FH + cc] =
                    *(const float4*)&aw_W1[(size_t)(k0+row)*FH + cc];
            }
            __syncthreads();
            #pragma unroll
            for (int kk=0;kk<16;kk++) {
                float a0 = Xs[r0*FDIM + k0+kk];
                float a1 = Xs[(r0+1)*FDIM + k0+kk];
                float2 b = *(float2*)&Ws[kk*FH + hc0];
                acc[0][0]=fmaf(a0,b.x,acc[0][0]); acc[0][1]=fmaf(a0,b.y,acc[0][1]);
                acc[1][0]=fmaf(a1,b.x,acc[1][0]); acc[1][1]=fmaf(a1,b.y,acc[1][1]);
            }
        }
        float2 b1v = *(const float2*)&aw_b1[hc0];
        float2 w2v = *(const float2*)&aw_W2[hc0];
        float ep[2];
        #pragma unroll
        for (int m=0;m<2;m++) {
            float pre0 = acc[m][0] + b1v.x;
            float pre1 = acc[m][1] + b1v.y;
            float sg0 = 1.f/(1.f+expf(-pre0));
            float sg1 = 1.f/(1.f+expf(-pre1));
            ep[m] = sspf(pre0)*w2v.x + sspf(pre1)*w2v.y;
            Ts[(r0+m)*FH + hc0 + 0] = sg0*w2v.x;
            Ts[(r0+m)*FH + hc0 + 1] = sg1*w2v.y;
        }
        #pragma unroll
        for (int o=16;o>0;o>>=1) {
            ep[0] += __shfl_xor_sync(0xffffffffu, ep[0], o);
            ep[1] += __shfl_xor_sync(0xffffffffu, ep[1], o);
        }
        if (cg == 0) { es[r0] = ep[0]; es[r0+1] = ep[1]; }
        __syncthreads();
        if (tid == 0) {
            float s = APM * aw_b2[0];
            #pragma unroll
            for (int a=0;a<APM;a++) s += es[a];
            out[(size_t)3*NATOMS + mol] = s;
        }
        float acc2[2][4] = {};
        for (int k0=0;k0<FH;k0+=16) {
            __syncthreads();
            {
                int f = tid>>2, kq = (tid&3)<<2;
                float4 w = *(const float4*)&aw_W1[(size_t)f*FH + k0 + kq];
                Ws[(kq+0)*FDIM + f] = w.x;
                Ws[(kq+1)*FDIM + f] = w.y;
                Ws[(kq+2)*FDIM + f] = w.z;
                Ws[(kq+3)*FDIM + f] = w.w;
            }
            __syncthreads();
            #pragma unroll
            for (int kk=0;kk<16;kk++) {
                float a0 = Ts[r0*FH + k0+kk];
                float a1 = Ts[(r0+1)*FH + k0+kk];
                float4 b = *(float4*)&Ws[kk*FDIM + c0];
                acc2[0][0]=fmaf(a0,b.x,acc2[0][0]); acc2[0][1]=fmaf(a0,b.y,acc2[0][1]);
                acc2[0][2]=fmaf(a0,b.z,acc2[0][2]); acc2[0][3]=fmaf(a0,b.w,acc2[0][3]);
                acc2[1][0]=fmaf(a1,b.x,acc2[1][0]); acc2[1][1]=fmaf(a1,b.y,acc2[1][1]);
                acc2[1][2]=fmaf(a1,b.z,acc2[1][2]); acc2[1][3]=fmaf(a1,b.w,acc2[1][3]);
            }
        }
        __syncthreads();
        #pragma unroll
        for (int m=0;m<2;m++)
            *(float4*)&Xs[(r0+m)*FDIM + c0] =
                make_float4(acc2[m][0],acc2[m][1],acc2[m][2],acc2[m][3]);
    }

    // =============== backward layers ===============
    for (int l = NLAY-1; l >= 0; l--) {
        const float* W0 = in2f_W + (size_t)l*FDIM*FDIM;
        const float* W1 = f2_W1  + (size_t)l*FDIM*FDIM;
        const float* W2 = f2_W2  + (size_t)l*FDIM*FDIM;
        const float* FWl = FWng + (size_t)l*TABF*FDIM;
        const float* Gl  = Gng  + (size_t)l*TABF*FDIM;
        const float* s_g = g_sig2_ + (size_t)l*NF;
        const float* h_g = g_h_ + (size_t)l*NF;

        if (l < 2) {
            for (int t=tid; t<APM*FDIM/4; t+=512) {
                int a = t>>5, f4 = (t&31)<<2;
                *(float4*)&Hs[a*FDIM + f4] =
                    *(const float4*)&h_g[(size_t)(abase+a)*FDIM + f4];
            }
        }

        float acc[4][4];
        gemm128<true>(Xs, W2, Ws, tid, acc);
        if (tid < 256) {
            #pragma unroll
            for (int m=0;m<4;m++) {
                float4 s4 = *(const float4*)&s_g[(size_t)(abase+r4+m)*FDIM + c4];
                Ts[(r4+m)*FDIM + c4 + 0] = acc[m][0]*s4.x;
                Ts[(r4+m)*FDIM + c4 + 1] = acc[m][1]*s4.y;
                Ts[(r4+m)*FDIM + c4 + 2] = acc[m][2]*s4.z;
                Ts[(r4+m)*FDIM + c4 + 3] = acc[m][3]*s4.w;
            }
        }

        gemm128<true>(Ts, W1, Ws, tid, acc);
        if (tid < 256) {
            #pragma unroll
            for (int m=0;m<4;m++)
                *(float4*)&As[(r4+m)*FDIM + c4] =
                    make_float4(acc[m][0],acc[m][1],acc[m][2],acc[m][3]);
        }
        __syncthreads();

        // fused gh + gd, 2 edges per butterfly
        #pragma unroll
        for (int it=0; it<2; it++) {
            int j = it*16 + slot;
            int cnt = cntJ[j];
            ulonglong2 hj = *(const ulonglong2*)&Hs[j*FDIM + l4];
            ull a0=0ull, a1=0ull;
            int c = 0;
            for (; c+1 < cnt; c += 2) {
                int pkA = __float_as_int(liJ[j*31+c]);
                int pkB = __float_as_int(liJ[j*31+c+1]);
                int iA = pkA >> 19, sA = (pkA >> 14) & 31, TA = pkA & 16383;
                int iB = pkB >> 19, sB = (pkB >> 14) & 31, TB = pkB & 16383;
                ulonglong2 wA  = *(const ulonglong2*)&FWl[(size_t)TA*FDIM + l4];
                ulonglong2 wB  = *(const ulonglong2*)&FWl[(size_t)TB*FDIM + l4];
                ulonglong2 gvA = *(const ulonglong2*)&Gl[(size_t)TA*FDIM + l4];
                ulonglong2 gvB = *(const ulonglong2*)&Gl[(size_t)TB*FDIM + l4];
                ulonglong2 gaA = *(const ulonglong2*)&As[iA*FDIM + l4];
                ulonglong2 gaB = *(const ulonglong2*)&As[iB*FDIM + l4];
                a0 = fma2(gaA.x, wA.x, a0);
                a1 = fma2(gaA.y, wA.y, a1);
                a0 = fma2(gaB.x, wB.x, a0);
                a1 = fma2(gaB.y, wB.y, a1);
                ull sAa = mul2(mul2(gaA.x, hj.x), gvA.x);
                sAa = fma2(mul2(gaA.y, hj.y), gvA.y, sAa);
                ull sBa = mul2(mul2(gaB.x, hj.x), gvB.x);
                sBa = fma2(mul2(gaB.y, hj.y), gvB.y, sBa);
                float2 svA = upk(sAa), svB = upk(sBa);
                ull tp = pk2f(svA.x + svA.y, svB.x + svB.y);
                #pragma unroll
                for (int o=16;o>0;o>>=1) {
                    float2 th = upk(tp);
                    float lx = __shfl_xor_sync(0xffffffffu, th.x, o);
                    float ly = __shfl_xor_sync(0xffffffffu, th.y, o);
                    tp = add2(tp, pk2f(lx, ly));
                }
                if (lane == 0) {
                    float2 tr = upk(tp);
                    gd_s[iA*31+sA] += tr.x;
                    gd_s[iB*31+sB] += tr.y;
                }
            }
            if (c < cnt) {
                int pk = __float_as_int(liJ[j*31+c]);
                int i = pk >> 19, slotI = (pk >> 14) & 31, T = pk & 16383;
                ulonglong2 w  = *(const ulonglong2*)&FWl[(size_t)T*FDIM + l4];
                ulonglong2 gv = *(const ulonglong2*)&Gl[(size_t)T*FDIM + l4];
                ulonglong2 ga = *(const ulonglong2*)&As[i*FDIM + l4];
                a0 = fma2(ga.x, w.x, a0);
                a1 = fma2(ga.y, w.y, a1);
                ull s = mul2(mul2(ga.x, hj.x), gv.x);
                s = fma2(mul2(ga.y, hj.y), gv.y, s);
                float2 sv = upk(s);
                float term = sv.x + sv.y;
                #pragma unroll
                for (int o=16;o>0;o>>=1)
                    term += __shfl_xor_sync(0xffffffffu, term, o);
                if (lane == 0) gd_s[i*31+slotI] += term;
            }
            ulonglong2 r; r.x=a0; r.y=a1;
            *(ulonglong2*)&Ts[j*FDIM + l4] = r;
        }

        gemm128<true>(Ts, W0, Ws, tid, acc);
        if (tid < 256) {
            #pragma unroll
            for (int m=0;m<4;m++) {
                float* gp = &Xs[(r4+m)*FDIM + c4];
                gp[0] += acc[m][0]; gp[1] += acc[m][1];
                gp[2] += acc[m][2]; gp[3] += acc[m][3];
            }
        }
    }
    __syncthreads();

    // =============== action ===============
    {
        float* gp  = Ws;
        float* nrm = Ws + 96;
        float* cf  = Ws + 128;
        if (tid < 96) gp[tid] = 0.f;
        __syncthreads();
        for (int el=tid; el<APM*31; el+=512) {
            int i = el / 31, slot2 = el - i*31;
            if (slot2 < cntI[i]) {
                int pk = __float_as_int(liI[el]);
                int j = pk >> 14;
                float rx = pos_s[j*3+0]-pos_s[i*3+0];
                float ry = pos_s[j*3+1]-pos_s[i*3+1];
                float rz = pos_s[j*3+2]-pos_s[i*3+2];
                float d = sqrtf(rx*rx+ry*ry+rz*rz + 1e-12f);
                float g = gd_s[el] / d;
                atomicAdd(&gp[j*3+0],  g*rx); atomicAdd(&gp[j*3+1],  g*ry);
                atomicAdd(&gp[j*3+2],  g*rz);
                atomicAdd(&gp[i*3+0], -g*rx); atomicAdd(&gp[i*3+1], -g*ry);
                atomicAdd(&gp[i*3+2], -g*rz);
            }
        }
        __syncthreads();
        if (tid < APM) {
            float ax = gp[tid*3+0], ay = gp[tid*3+1], az = gp[tid*3+2];
            nrm[tid] = sqrtf(ax*ax + ay*ay + az*az);
        }
        __syncthreads();
        if (tid == 0) {
            float mx = 0.f;
            #pragma unroll
            for (int a=0;a<APM;a++) mx = fmaxf(mx, nrm[a]);
            cf[0] = fminf(1.0f / fmaxf(mx, 1e-8f), 1.0f);
        }
        __syncthreads();
        float coef = cf[0];
        for (int t=tid; t<96; t+=512)
            out[(size_t)abase*3 + t] = -gp[t]*coef;
    }
}

// ---------------- host ----------------
static const int MEGA_SMEM = SM_FLOATS * 4;

extern "C" void kernel_launch(void* const* d_in, const int* in_sizes, int n_in,
                              void* d_out, int out_size)
{
    const float* positions = (const float*)d_in[0];
    const float* emb       = (const float*)d_in[1];
    const float* in2f_W    = (const float*)d_in[2];
    const float* filt_W1   = (const float*)d_in[3];
    const float* filt_b1   = (const float*)d_in[4];
    const float* filt_W2   = (const float*)d_in[5];
    const float* filt_b2   = (const float*)d_in[6];
    const float* f2_W1     = (const float*)d_in[7];
    const float* f2_b1     = (const float*)d_in[8];
    const float* f2_W2     = (const float*)d_in[9];
    const float* f2_b2     = (const float*)d_in[10];
    const float* aw_W1     = (const float*)d_in[11];
    const float* aw_b1     = (const float*)d_in[12];
    const float* aw_W2     = (const float*)d_in[13];
    const float* aw_b2     = (const float*)d_in[14];
    const int*   Z         = (const int*)d_in[15];
    float* out = (float*)d_out;

    float *p_h, *p_sig2, *p_tabW, *p_tabD, *p_FWn, *p_Gn;
    cudaGetSymbolAddress((void**)&p_h,     g_h);
    cudaGetSymbolAddress((void**)&p_sig2,  g_sig2);
    cudaGetSymbolAddress((void**)&p_tabW,  g_tabW);
    cudaGetSymbolAddress((void**)&p_tabD,  g_tabD);
    cudaGetSymbolAddress((void**)&p_FWn,   g_FWn);
    cudaGetSymbolAddress((void**)&p_Gn,    g_Gn);

    cudaFuncSetAttribute(mega_k, cudaFuncAttributeMaxDynamicSharedMemorySize,
                         MEGA_SMEM);

    table_k<<<dim3(TABN/8,3),128>>>(filt_W1, filt_b1, filt_W2, filt_b2,
                                    p_tabW, p_tabD);
    upsample_k<<<dim3(TABF,3),128>>>(p_tabW, p_tabD, p_FWn, p_Gn);
    mega_k<<<NMOL, 512, MEGA_SMEM>>>(
        positions, emb, Z, in2f_W,
        f2_W1, f2_b1, f2_W2, f2_b2,
        aw_W1, aw_b1, aw_W2, aw_b2,
        p_FWn, p_Gn, p_h, p_sig2, out);
}

// round 17
// speedup vs baseline: 1.1897x; 1.0266x over previous
#include <cuda_runtime.h>
#include <math.h>

// ---------------- problem constants ----------------
#define NATOMS 16384
#define NMOL   512
#define APM    32
#define FDIM   128
#define NRBF   20
#define FH     64
#define NLAY   3
#define PI_F   3.14159265358979f
#define CUT    5.0f
#define LOG2_F 0.6931471805599453f
#define TABN   1024
#define TABF   16384
#define TPTS   4

static const size_t NF = (size_t)NATOMS * FDIM;

typedef unsigned long long ull;

// ---------------- scratch ----------------
__device__ __align__(16) float  g_h    [3 * NF];
__device__ __align__(16) float  g_sig2 [3 * NF];
__device__ __align__(16) float  g_tabW [3 * TABN * FDIM];
__device__ __align__(16) float  g_tabD [3 * TABN * FDIM];
__device__ __align__(16) float  g_FWn  [3 * (size_t)TABF * FDIM];
__device__ __align__(16) float  g_Gn   [3 * (size_t)TABF * FDIM];

__device__ __forceinline__ float sspf(float v) {
    return fmaxf(v, 0.f) + log1pf(expf(-fabsf(v))) - LOG2_F;
}
__device__ __forceinline__ ull pk2(float x) {
    ull r; asm("mov.b64 %0, {%1, %1};" : "=l"(r) : "f"(x)); return r;
}
__device__ __forceinline__ ull pk2f(float x, float y) {
    ull r; asm("mov.b64 %0, {%1, %2};" : "=l"(r) : "f"(x), "f"(y)); return r;
}
__device__ __forceinline__ ull fma2(ull a, ull b, ull c) {
    ull d; asm("fma.rn.f32x2 %0, %1, %2, %3;" : "=l"(d) : "l"(a), "l"(b), "l"(c)); return d;
}
__device__ __forceinline__ ull mul2(ull a, ull b) {
    ull d; asm("mul.rn.f32x2 %0, %1, %2;" : "=l"(d) : "l"(a), "l"(b)); return d;
}
__device__ __forceinline__ ull add2(ull a, ull b) {
    ull d; asm("add.rn.f32x2 %0, %1, %2;" : "=l"(d) : "l"(a), "l"(b)); return d;
}
__device__ __forceinline__ float2 upk(ull v) {
    float2 r; asm("mov.b64 {%0, %1}, %2;" : "=f"(r.x), "=f"(r.y) : "l"(v)); return r;
}

// ---------------- coarse table build: TPTS points per block ----------------
__global__ __launch_bounds__(128) void table_k(
    const float* __restrict__ W1, const float* __restrict__ b1,
    const float* __restrict__ W2, const float* __restrict__ b2,
    float* __restrict__ tabW, float* __restrict__ tabD)
{
    const int tb = blockIdx.x;
    const int l  = blockIdx.y;
    const int f  = threadIdx.x;
    const float DELTA = CUT / (NRBF-1);
    const float CO = -0.5f / (DELTA*DELTA);

    __shared__ float rbf_s [TPTS*NRBF];
    __shared__ float drbf_s[TPTS*NRBF];
    __shared__ float t1_s [FDIM*TPTS];
    __shared__ float dt1_s[FDIM*TPTS];

    for (int t = f; t < TPTS*NRBF; t += 128) {
        int pt = t / NRBF, k = t % NRBF;
        float d = (tb*TPTS + pt) * (CUT/(float)(TABN-1));
        float u = d - k*DELTA;
        float g = expf(CO*u*u);
        rbf_s[t]  = g;
        drbf_s[t] = g * (2.f*CO*u);
    }
    __syncthreads();

    const float* W1l = W1 + (size_t)l*NRBF*FDIM;
    float p[TPTS], dp[TPTS];
    float bb1 = b1[l*FDIM + f];
    #pragma unroll
    for (int pt=0;pt<TPTS;pt++) { p[pt]=bb1; dp[pt]=0.f; }
    #pragma unroll
    for (int k=0;k<NRBF;k++) {
        float w = W1l[k*FDIM + f];
        #pragma unroll
        for (int pt=0;pt<TPTS;pt++) {
            p[pt]  = fmaf(rbf_s [pt*NRBF+k], w, p[pt]);
            dp[pt] = fmaf(drbf_s[pt*NRBF+k], w, dp[pt]);
        }
    }
    #pragma unroll
    for (int pt=0;pt<TPTS;pt++) {
        float sg = 1.f/(1.f+expf(-p[pt]));
        t1_s [f*TPTS+pt] = sspf(p[pt]);
        dt1_s[f*TPTS+pt] = sg*dp[pt];
    }
    __syncthreads();

    const float* W2l = W2 + (size_t)l*FDIM*FDIM;
    float w[TPTS], dw[TPTS];
    float bb2 = b2[l*FDIM + f];
    #pragma unroll
    for (int pt=0;pt<TPTS;pt++) { w[pt]=bb2; dw[pt]=0.f; }
    for (int c=0;c<FDIM;c++) {
        float wv = W2l[(size_t)c*FDIM + f];
        float4 ta = *(const float4*)&t1_s [c*TPTS];
        float4 da = *(const float4*)&dt1_s[c*TPTS];
        w[0]=fmaf(ta.x,wv,w[0]); w[1]=fmaf(ta.y,wv,w[1]);
        w[2]=fmaf(ta.z,wv,w[2]); w[3]=fmaf(ta.w,wv,w[3]);
        dw[0]=fmaf(da.x,wv,dw[0]); dw[1]=fmaf(da.y,wv,dw[1]);
        dw[2]=fmaf(da.z,wv,dw[2]); dw[3]=fmaf(da.w,wv,dw[3]);
    }
    #pragma unroll
    for (int pt=0;pt<TPTS;pt++) {
        size_t o = ((size_t)l*TABN + tb*TPTS + pt)*FDIM + f;
        tabW[o] = w[pt];
        tabD[o] = dw[pt];
    }
}

// ---------------- upsample to fine nearest-neighbor tables ----------------
__global__ __launch_bounds__(128) void upsample_k(
    const float* __restrict__ tabW, const float* __restrict__ tabD,
    float* __restrict__ FWn, float* __restrict__ Gn)
{
    const int T = blockIdx.x, l = blockIdx.y, f = threadIdx.x;
    const float dfine = T * (CUT/(float)(TABF-1));
    float x = dfine * ((float)(TABN-1)/CUT);
    int t0 = (int)x; if (t0 > TABN-2) t0 = TABN-2;
    float fr = x - (float)t0;
    size_t oc = ((size_t)l*TABN + t0)*FDIM + f;
    float w0 = tabW[oc], w1 = tabW[oc+FDIM];
    float d0 = tabD[oc], d1 = tabD[oc+FDIM];
    float w = fmaf(fr, w1-w0, w0);
    float dd = fmaf(fr, d1-d0, d0);
    float ang = PI_F * dfine * (1.f/CUT);
    float fc  = 0.5f*(cosf(ang)+1.f);
    float dfc = -(0.5f*PI_F/CUT)*sinf(ang);
    size_t of = ((size_t)l*TABF + T)*FDIM + f;
    FWn[of] = fc*w;
    Gn[of]  = fmaf(fc, dd, dfc*w);
}

// ---------------- GEMM: chunk-32, double-buffered, K-split-2, 4x4 tiles ----
template<bool TRANSB>
__device__ __forceinline__ void ldW32(float* Wd, const float* __restrict__ Bg,
                                      int k0, int tid)
{
    if (!TRANSB) {
        int row = tid>>4, c8 = (tid&15)<<3;     // 32 rows x 128 cols
        *(float4*)&Wd[row*FDIM + c8] =
            *(const float4*)&Bg[(size_t)(k0+row)*FDIM + c8];
        *(float4*)&Wd[row*FDIM + c8+4] =
            *(const float4*)&Bg[(size_t)(k0+row)*FDIM + c8+4];
    } else {
        int c = tid>>2, kq = (tid&3)<<3;        // 8 k's per thread, col c
        float4 w0 = *(const float4*)&Bg[(size_t)c*FDIM + k0 + kq];
        float4 w1 = *(const float4*)&Bg[(size_t)c*FDIM + k0 + kq + 4];
        Wd[(kq+0)*FDIM + c] = w0.x;
        Wd[(kq+1)*FDIM + c] = w0.y;
        Wd[(kq+2)*FDIM + c] = w0.z;
        Wd[(kq+3)*FDIM + c] = w0.w;
        Wd[(kq+4)*FDIM + c] = w1.x;
        Wd[(kq+5)*FDIM + c] = w1.y;
        Wd[(kq+6)*FDIM + c] = w1.z;
        Wd[(kq+7)*FDIM + c] = w1.w;
    }
}

template<bool TRANSB>
__device__ __forceinline__ void gemm128(const float* __restrict__ A_s,
                                        const float* __restrict__ Bg,
                                        float* Ws, int tid, float out[4][4])
{
    const int kh = tid >> 8;
    const int t  = tid & 255;
    const int r4 = (t >> 5) << 2;
    const int c4 = (t & 31) << 2;
    ull acc[4][2] = {};
    ldW32<TRANSB>(Ws, Bg, 0, tid);
    __syncthreads();
    for (int ch=0; ch<4; ch++) {
        const float* Wc = Ws + (ch&1)*4096;
        if (ch < 3) ldW32<TRANSB>(Ws + ((ch+1)&1)*4096, Bg, (ch+1)*32, tid);
        if ((ch>>1) == kh) {
            const int k0 = ch*32;
            #pragma unroll
            for (int kq=0; kq<32; kq+=4) {
                float4 av0 = *(const float4*)&A_s[(r4+0)*FDIM + k0+kq];
                float4 av1 = *(const float4*)&A_s[(r4+1)*FDIM + k0+kq];
                float4 av2 = *(const float4*)&A_s[(r4+2)*FDIM + k0+kq];
                float4 av3 = *(const float4*)&A_s[(r4+3)*FDIM + k0+kq];
                const float* a0p = (const float*)&av0;
                const float* a1p = (const float*)&av1;
                const float* a2p = (const float*)&av2;
                const float* a3p = (const float*)&av3;
                #pragma unroll
                for (int kk=0;kk<4;kk++) {
                    ull a0 = pk2(a0p[kk]);
                    ull a1 = pk2(a1p[kk]);
                    ull a2 = pk2(a2p[kk]);
                    ull a3 = pk2(a3p[kk]);
                    ulonglong2 bp = *(const ulonglong2*)&Wc[(kq+kk)*FDIM + c4];
                    acc[0][0]=fma2(a0,bp.x,acc[0][0]); acc[0][1]=fma2(a0,bp.y,acc[0][1]);
                    acc[1][0]=fma2(a1,bp.x,acc[1][0]); acc[1][1]=fma2(a1,bp.y,acc[1][1]);
                    acc[2][0]=fma2(a2,bp.x,acc[2][0]); acc[2][1]=fma2(a2,bp.y,acc[2][1]);
                    acc[3][0]=fma2(a3,bp.x,acc[3][0]); acc[3][1]=fma2(a3,bp.y,acc[3][1]);
                }
            }
        }
        __syncthreads();
    }
    ull* buf = (ull*)Ws;
    if (kh == 1) {
        ull* bp = buf + t*8;
        #pragma unroll
        for (int m=0;m<4;m++) { bp[m*2]=acc[m][0]; bp[m*2+1]=acc[m][1]; }
    }
    __syncthreads();
    if (kh == 0) {
        const ull* bp = buf + t*8;
        #pragma unroll
        for (int m=0;m<4;m++) {
            float2 p0 = upk(acc[m][0]), q0 = upk(bp[m*2]);
            float2 p1 = upk(acc[m][1]), q1 = upk(bp[m*2+1]);
            out[m][0]=p0.x+q0.x; out[m][1]=p0.y+q0.y;
            out[m][2]=p1.x+q1.x; out[m][3]=p1.y+q1.y;
        }
    }
    __syncthreads();
}

// ---------------- smem pool (floats) ----------------
#define OFF_XS   0
#define OFF_HS   (OFF_XS + APM*FDIM)
#define OFF_AS   (OFF_HS + APM*FDIM)
#define OFF_TS   (OFF_AS + APM*FDIM)
#define OFF_WS   (OFF_TS + APM*FDIM)        // 2 x 4096 (also reduction buffer)
#define OFF_LI   (OFF_WS + 8192)
#define OFF_LJ   (OFF_LI + APM*31)
#define OFF_GD   (OFF_LJ + APM*31)
#define OFF_POS  (OFF_GD + APM*31)
#define OFF_PIJ  (OFF_POS + 96)
#define OFF_CNT  (OFF_PIJ + 256)
#define OFF_ES   (OFF_CNT + 64)
#define SM_FLOATS (OFF_ES + 32)

__global__ __launch_bounds__(512,2) void mega_k(
    const float* __restrict__ pos, const float* __restrict__ emb,
    const int* __restrict__ Z,
    const float* __restrict__ in2f_W,
    const float* __restrict__ f2_W1, const float* __restrict__ f2_b1,
    const float* __restrict__ f2_W2, const float* __restrict__ f2_b2,
    const float* __restrict__ aw_W1, const float* __restrict__ aw_b1,
    const float* __restrict__ aw_W2, const float* __restrict__ aw_b2,
    const float* __restrict__ FWng, const float* __restrict__ Gng,
    float* __restrict__ g_h_, float* __restrict__ g_sig2_,
    float* __restrict__ out)
{
    extern __shared__ float sm[];
    float*  Xs    = sm + OFF_XS;
    float*  Hs    = sm + OFF_HS;
    float*  As    = sm + OFF_AS;
    float*  Ts    = sm + OFF_TS;
    float*  Ws    = sm + OFF_WS;
    float*  liI   = sm + OFF_LI;
    float*  liJ   = sm + OFF_LJ;
    float*  gd_s  = sm + OFF_GD;
    float*  pos_s = sm + OFF_POS;
    unsigned char* posIJ = (unsigned char*)(sm + OFF_PIJ);
    int*    cntI  = (int*)(sm + OFF_CNT);
    int*    cntJ  = cntI + 32;
    float*  es    = sm + OFF_ES;

    const int tid = threadIdx.x;
    const int mol = blockIdx.x;
    const int abase = mol*APM;

    const int rg = tid>>5, cg = tid&31;
    const int r0 = rg<<1, c0 = cg<<2;
    const int q  = tid & 255;
    const int r4 = (q>>5)<<2, c4 = (q&31)<<2;
    const int slot = tid>>5, lane = tid&31;
    const int l4 = lane<<2;

    // ---------- P0 ----------
    if (tid < 96) pos_s[tid] = pos[abase*3 + tid];
    for (int t=tid; t<APM*FDIM/4; t+=512) {
        int a = t>>5, f4 = (t&31)<<2;
        int z = Z[abase + a];
        *(float4*)&Xs[a*FDIM + f4] = *(const float4*)&emb[(size_t)z*FDIM + f4];
    }
    for (int t=tid; t<APM*31; t+=512) gd_s[t] = 0.f;
    __syncthreads();

    // ---------- edge lists ----------
    if (tid < 32) {
        const int a = tid;
        int count = 0;
        for (int c=0; c<31; c++) {
            int j = c + (c >= a ? 1 : 0);
            float rx = pos_s[j*3+0]-pos_s[a*3+0];
            float ry = pos_s[j*3+1]-pos_s[a*3+1];
            float rz = pos_s[j*3+2]-pos_s[a*3+2];
            float d = sqrtf(rx*rx+ry*ry+rz*rz + 1e-12f);
            if (d < CUT) {
                int T = (int)(d * ((float)(TABF-1)/CUT) + 0.5f);
                if (T > TABF-1) T = TABF-1;
                liI[a*31+count] = __int_as_float((j << 14) | T);
                posIJ[a*32 + j] = (unsigned char)count;
                count++;
            }
        }
        cntI[a] = count;
    }
    __syncthreads();
    if (tid < 32) {
        const int a = tid;
        int count = 0;
        for (int c=0; c<31; c++) {
            int i = c + (c >= a ? 1 : 0);
            float rx = pos_s[a*3+0]-pos_s[i*3+0];
            float ry = pos_s[a*3+1]-pos_s[i*3+1];
            float rz = pos_s[a*3+2]-pos_s[i*3+2];
            float d = sqrtf(rx*rx+ry*ry+rz*rz + 1e-12f);
            if (d < CUT) {
                int T = (int)(d * ((float)(TABF-1)/CUT) + 0.5f);
                if (T > TABF-1) T = TABF-1;
                int slotI = posIJ[i*32 + a];
                liJ[a*31+count] = __int_as_float((i << 19) | (slotI << 14) | T);
                count++;
            }
        }
        cntJ[a] = count;
    }

    // =============== forward layers ===============
    for (int l = 0; l < NLAY; l++) {
        const float* W0 = in2f_W + (size_t)l*FDIM*FDIM;
        const float* W1 = f2_W1  + (size_t)l*FDIM*FDIM;
        const float* W2 = f2_W2  + (size_t)l*FDIM*FDIM;
        const float* FWl = FWng + (size_t)l*TABF*FDIM;
        float* s_g = g_sig2_ + (size_t)l*NF;
        float* h_g = g_h_ + (size_t)l*NF;

        float acc[4][4];
        gemm128<false>(Xs, W0, Ws, tid, acc);
        if (tid < 256) {
            #pragma unroll
            for (int m=0;m<4;m++) {
                float4 v = make_float4(acc[m][0],acc[m][1],acc[m][2],acc[m][3]);
                *(float4*)&Hs[(r4+m)*FDIM + c4] = v;
                if (l < 2)
                    *(float4*)&h_g[(size_t)(abase+r4+m)*FDIM + c4] = v;
            }
        }
        __syncthreads();

        // agg
        #pragma unroll
        for (int it=0; it<2; it++) {
            int i = it*16 + slot;
            int cnt = cntI[i];
            ull a0=0ull, a1=0ull;
            for (int c=0;c<cnt;c++) {
                int pk = __float_as_int(liI[i*31+c]);
                int j = pk >> 14;
                int T = pk & 16383;
                ulonglong2 w = *(const ulonglong2*)&FWl[(size_t)T*FDIM + l4];
                ulonglong2 h = *(const ulonglong2*)&Hs[j*FDIM + l4];
                a0 = fma2(h.x, w.x, a0);
                a1 = fma2(h.y, w.y, a1);
            }
            ulonglong2 r; r.x=a0; r.y=a1;
            *(ulonglong2*)&As[i*FDIM + l4] = r;
        }

        gemm128<false>(As, W1, Ws, tid, acc);
        if (tid < 256) {
            float4 b1v = *(const float4*)&f2_b1[l*FDIM + c4];
            float bb[4]={b1v.x,b1v.y,b1v.z,b1v.w};
            #pragma unroll
            for (int m=0;m<4;m++) {
                float sg4[4];
                #pragma unroll
                for (int n=0;n<4;n++) {
                    float pre = acc[m][n] + bb[n];
                    sg4[n] = 1.f/(1.f+expf(-pre));
                    Ts[(r4+m)*FDIM + c4 + n] = sspf(pre);
                }
                *(float4*)&s_g[(size_t)(abase+r4+m)*FDIM + c4] =
                    make_float4(sg4[0],sg4[1],sg4[2],sg4[3]);
            }
        }

        gemm128<false>(Ts, W2, Ws, tid, acc);
        if (tid < 256) {
            float4 b2v = *(const float4*)&f2_b2[l*FDIM + c4];
            #pragma unroll
            for (int m=0;m<4;m++) {
                float* xp = &Xs[(r4+m)*FDIM + c4];
                xp[0] += acc[m][0] + b2v.x;
                xp[1] += acc[m][1] + b2v.y;
                xp[2] += acc[m][2] + b2v.z;
                xp[3] += acc[m][3] + b2v.w;
            }
        }
    }

    // =============== head ===============
    {
        if (tid < APM) es[tid] = 0.f;
        const int hc0 = cg<<1;
        float acc[2][2] = {};
        for (int k0=0;k0<FDIM;k0+=16) {
            __syncthreads();
            if (tid < 256) {
                int row = tid>>4, cc = (tid&15)<<2;
                *(float4*)&Ws[row*FH + cc] =
                    *(const float4*)&aw_W1[(size_t)(k0+row)*FH + cc];
            }
            __syncthreads();
            #pragma unroll
            for (int kk=0;kk<16;kk++) {
                float a0 = Xs[r0*FDIM + k0+kk];
                float a1 = Xs[(r0+1)*FDIM + k0+kk];
                float2 b = *(float2*)&Ws[kk*FH + hc0];
                acc[0][0]=fmaf(a0,b.x,acc[0][0]); acc[0][1]=fmaf(a0,b.y,acc[0][1]);
                acc[1][0]=fmaf(a1,b.x,acc[1][0]); acc[1][1]=fmaf(a1,b.y,acc[1][1]);
            }
        }
        float2 b1v = *(const float2*)&aw_b1[hc0];
        float2 w2v = *(const float2*)&aw_W2[hc0];
        float ep[2];
        #pragma unroll
        for (int m=0;m<2;m++) {
            float pre0 = acc[m][0] + b1v.x;
            float pre1 = acc[m][1] + b1v.y;
            float sg0 = 1.f/(1.f+expf(-pre0));
            float sg1 = 1.f/(1.f+expf(-pre1));
            ep[m] = sspf(pre0)*w2v.x + sspf(pre1)*w2v.y;
            Ts[(r0+m)*FH + hc0 + 0] = sg0*w2v.x;
            Ts[(r0+m)*FH + hc0 + 1] = sg1*w2v.y;
        }
        #pragma unroll
        for (int o=16;o>0;o>>=1) {
            ep[0] += __shfl_xor_sync(0xffffffffu, ep[0], o);
            ep[1] += __shfl_xor_sync(0xffffffffu, ep[1], o);
        }
        if (cg == 0) { es[r0] = ep[0]; es[r0+1] = ep[1]; }
        __syncthreads();
        if (tid == 0) {
            float s = APM * aw_b2[0];
            #pragma unroll
            for (int a=0;a<APM;a++) s += es[a];
            out[(size_t)3*NATOMS + mol] = s;
        }
        float acc2[2][4] = {};
        for (int k0=0;k0<FH;k0+=16) {
            __syncthreads();
            {
                int f = tid>>2, kq = (tid&3)<<2;
                float4 w = *(const float4*)&aw_W1[(size_t)f*FH + k0 + kq];
                Ws[(kq+0)*FDIM + f] = w.x;
                Ws[(kq+1)*FDIM + f] = w.y;
                Ws[(kq+2)*FDIM + f] = w.z;
                Ws[(kq+3)*FDIM + f] = w.w;
            }
            __syncthreads();
            #pragma unroll
            for (int kk=0;kk<16;kk++) {
                float a0 = Ts[r0*FH + k0+kk];
                float a1 = Ts[(r0+1)*FH + k0+kk];
                float4 b = *(float4*)&Ws[kk*FDIM + c0];
                acc2[0][0]=fmaf(a0,b.x,acc2[0][0]); acc2[0][1]=fmaf(a0,b.y,acc2[0][1]);
                acc2[0][2]=fmaf(a0,b.z,acc2[0][2]); acc2[0][3]=fmaf(a0,b.w,acc2[0][3]);
                acc2[1][0]=fmaf(a1,b.x,acc2[1][0]); acc2[1][1]=fmaf(a1,b.y,acc2[1][1]);
                acc2[1][2]=fmaf(a1,b.z,acc2[1][2]); acc2[1][3]=fmaf(a1,b.w,acc2[1][3]);
            }
        }
        __syncthreads();
        #pragma unroll
        for (int m=0;m<2;m++)
            *(float4*)&Xs[(r0+m)*FDIM + c0] =
                make_float4(acc2[m][0],acc2[m][1],acc2[m][2],acc2[m][3]);
    }

    // =============== backward layers ===============
    for (int l = NLAY-1; l >= 0; l--) {
        const float* W0 = in2f_W + (size_t)l*FDIM*FDIM;
        const float* W1 = f2_W1  + (size_t)l*FDIM*FDIM;
        const float* W2 = f2_W2  + (size_t)l*FDIM*FDIM;
        const float* FWl = FWng + (size_t)l*TABF*FDIM;
        const float* Gl  = Gng  + (size_t)l*TABF*FDIM;
        const float* s_g = g_sig2_ + (size_t)l*NF;
        const float* h_g = g_h_ + (size_t)l*NF;

        if (l < 2) {
            for (int t=tid; t<APM*FDIM/4; t+=512) {
                int a = t>>5, f4 = (t&31)<<2;
                *(float4*)&Hs[a*FDIM + f4] =
                    *(const float4*)&h_g[(size_t)(abase+a)*FDIM + f4];
            }
        }

        float acc[4][4];
        gemm128<true>(Xs, W2, Ws, tid, acc);
        if (tid < 256) {
            #pragma unroll
            for (int m=0;m<4;m++) {
                float4 s4 = *(const float4*)&s_g[(size_t)(abase+r4+m)*FDIM + c4];
                Ts[(r4+m)*FDIM + c4 + 0] = acc[m][0]*s4.x;
                Ts[(r4+m)*FDIM + c4 + 1] = acc[m][1]*s4.y;
                Ts[(r4+m)*FDIM + c4 + 2] = acc[m][2]*s4.z;
                Ts[(r4+m)*FDIM + c4 + 3] = acc[m][3]*s4.w;
            }
        }

        gemm128<true>(Ts, W1, Ws, tid, acc);
        if (tid < 256) {
            #pragma unroll
            for (int m=0;m<4;m++)
                *(float4*)&As[(r4+m)*FDIM + c4] =
                    make_float4(acc[m][0],acc[m][1],acc[m][2],acc[m][3]);
        }
        __syncthreads();

        // fused gh + gd, 2 edges per butterfly
        #pragma unroll
        for (int it=0; it<2; it++) {
            int j = it*16 + slot;
            int cnt = cntJ[j];
            ulonglong2 hj = *(const ulonglong2*)&Hs[j*FDIM + l4];
            ull a0=0ull, a1=0ull;
            int c = 0;
            for (; c+1 < cnt; c += 2) {
                int pkA = __float_as_int(liJ[j*31+c]);
                int pkB = __float_as_int(liJ[j*31+c+1]);
                int iA = pkA >> 19, sA = (pkA >> 14) & 31, TA = pkA & 16383;
                int iB = pkB >> 19, sB = (pkB >> 14) & 31, TB = pkB & 16383;
                ulonglong2 wA  = *(const ulonglong2*)&FWl[(size_t)TA*FDIM + l4];
                ulonglong2 wB  = *(const ulonglong2*)&FWl[(size_t)TB*FDIM + l4];
                ulonglong2 gvA = *(const ulonglong2*)&Gl[(size_t)TA*FDIM + l4];
                ulonglong2 gvB = *(const ulonglong2*)&Gl[(size_t)TB*FDIM + l4];
                ulonglong2 gaA = *(const ulonglong2*)&As[iA*FDIM + l4];
                ulonglong2 gaB = *(const ulonglong2*)&As[iB*FDIM + l4];
                a0 = fma2(gaA.x, wA.x, a0);
                a1 = fma2(gaA.y, wA.y, a1);
                a0 = fma2(gaB.x, wB.x, a0);
                a1 = fma2(gaB.y, wB.y, a1);
                ull sAa = mul2(mul2(gaA.x, hj.x), gvA.x);
                sAa = fma2(mul2(gaA.y, hj.y), gvA.y, sAa);
                ull sBa = mul2(mul2(gaB.x, hj.x), gvB.x);
                sBa = fma2(mul2(gaB.y, hj.y), gvB.y, sBa);
                float2 svA = upk(sAa), svB = upk(sBa);
                ull tp = pk2f(svA.x + svA.y, svB.x + svB.y);
                #pragma unroll
                for (int o=16;o>0;o>>=1) {
                    float2 th = upk(tp);
                    float lx = __shfl_xor_sync(0xffffffffu, th.x, o);
                    float ly = __shfl_xor_sync(0xffffffffu, th.y, o);
                    tp = add2(tp, pk2f(lx, ly));
                }
                if (lane == 0) {
                    float2 tr = upk(tp);
                    gd_s[iA*31+sA] += tr.x;
                    gd_s[iB*31+sB] += tr.y;
                }
            }
            if (c < cnt) {
                int pk = __float_as_int(liJ[j*31+c]);
                int i = pk >> 19, slotI = (pk >> 14) & 31, T = pk & 16383;
                ulonglong2 w  = *(const ulonglong2*)&FWl[(size_t)T*FDIM + l4];
                ulonglong2 gv = *(const ulonglong2*)&Gl[(size_t)T*FDIM + l4];
                ulonglong2 ga = *(const ulonglong2*)&As[i*FDIM + l4];
                a0 = fma2(ga.x, w.x, a0);
                a1 = fma2(ga.y, w.y, a1);
                ull s = mul2(mul2(ga.x, hj.x), gv.x);
                s = fma2(mul2(ga.y, hj.y), gv.y, s);
                float2 sv = upk(s);
                float term = sv.x + sv.y;
                #pragma unroll
                for (int o=16;o>0;o>>=1)
                    term += __shfl_xor_sync(0xffffffffu, term, o);
                if (lane == 0) gd_s[i*31+slotI] += term;
            }
            ulonglong2 r; r.x=a0; r.y=a1;
            *(ulonglong2*)&Ts[j*FDIM + l4] = r;
        }

        gemm128<true>(Ts, W0, Ws, tid, acc);
        if (tid < 256) {
            #pragma unroll
            for (int m=0;m<4;m++) {
                float* gp = &Xs[(r4+m)*FDIM + c4];
                gp[0] += acc[m][0]; gp[1] += acc[m][1];
                gp[2] += acc[m][2]; gp[3] += acc[m][3];
            }
        }
    }
    __syncthreads();

    // =============== action ===============
    {
        float* gp  = Ws;
        float* nrm = Ws + 96;
        float* cf  = Ws + 128;
        if (tid < 96) gp[tid] = 0.f;
        __syncthreads();
        for (int el=tid; el<APM*31; el+=512) {
            int i = el / 31, slot2 = el - i*31;
            if (slot2 < cntI[i]) {
                int pk = __float_as_int(liI[el]);
                int j = pk >> 14;
                float rx = pos_s[j*3+0]-pos_s[i*3+0];
                float ry = pos_s[j*3+1]-pos_s[i*3+1];
                float rz = pos_s[j*3+2]-pos_s[i*3+2];
                float d = sqrtf(rx*rx+ry*ry+rz*rz + 1e-12f);
                float g = gd_s[el] / d;
                atomicAdd(&gp[j*3+0],  g*rx); atomicAdd(&gp[j*3+1],  g*ry);
                atomicAdd(&gp[j*3+2],  g*rz);
                atomicAdd(&gp[i*3+0], -g*rx); atomicAdd(&gp[i*3+1], -g*ry);
                atomicAdd(&gp[i*3+2], -g*rz);
            }
        }
        __syncthreads();
        if (tid < APM) {
            float ax = gp[tid*3+0], ay = gp[tid*3+1], az = gp[tid*3+2];
            nrm[tid] = sqrtf(ax*ax + ay*ay + az*az);
        }
        __syncthreads();
        if (tid == 0) {
            float mx = 0.f;
            #pragma unroll
            for (int a=0;a<APM;a++) mx = fmaxf(mx, nrm[a]);
            cf[0] = fminf(1.0f / fmaxf(mx, 1e-8f), 1.0f);
        }
        __syncthreads();
        float coef = cf[0];
        for (int t=tid; t<96; t+=512)
            out[(size_t)abase*3 + t] = -gp[t]*coef;
    }
}

// ---------------- host ----------------
static const int MEGA_SMEM = SM_FLOATS * 4;

extern "C" void kernel_launch(void* const* d_in, const int* in_sizes, int n_in,
                              void* d_out, int out_size)
{
    const float* positions = (const float*)d_in[0];
    const float* emb       = (const float*)d_in[1];
    const float* in2f_W    = (const float*)d_in[2];
    const float* filt_W1   = (const float*)d_in[3];
    const float* filt_b1   = (const float*)d_in[4];
    const float* filt_W2   = (const float*)d_in[5];
    const float* filt_b2   = (const float*)d_in[6];
    const float* f2_W1     = (const float*)d_in[7];
    const float* f2_b1     = (const float*)d_in[8];
    const float* f2_W2     = (const float*)d_in[9];
    const float* f2_b2     = (const float*)d_in[10];
    const float* aw_W1     = (const float*)d_in[11];
    const float* aw_b1     = (const float*)d_in[12];
    const float* aw_W2     = (const float*)d_in[13];
    const float* aw_b2     = (const float*)d_in[14];
    const int*   Z         = (const int*)d_in[15];
    float* out = (float*)d_out;

    float *p_h, *p_sig2, *p_tabW, *p_tabD, *p_FWn, *p_Gn;
    cudaGetSymbolAddress((void**)&p_h,     g_h);
    cudaGetSymbolAddress((void**)&p_sig2,  g_sig2);
    cudaGetSymbolAddress((void**)&p_tabW,  g_tabW);
    cudaGetSymbolAddress((void**)&p_tabD,  g_tabD);
    cudaGetSymbolAddress((void**)&p_FWn,   g_FWn);
    cudaGetSymbolAddress((void**)&p_Gn,    g_Gn);

    cudaFuncSetAttribute(mega_k, cudaFuncAttributeMaxDynamicSharedMemorySize,
                         MEGA_SMEM);

    table_k<<<dim3(TABN/TPTS,3),128>>>(filt_W1, filt_b1, filt_W2, filt_b2,
                                       p_tabW, p_tabD);
    upsample_k<<<dim3(TABF,3),128>>>(p_tabW, p_tabD, p_FWn, p_Gn);
    mega_k<<<NMOL, 512, MEGA_SMEM>>>(
        positions, emb, Z, in2f_W,
        f2_W1, f2_b1, f2_W2, f2_b2,
        aw_W1, aw_b1, aw_W2, aw_b2,
        p_FWn, p_Gn, p_h, p_sig2, out);
}